// round 9
// baseline (speedup 1.0000x reference)
#include <cuda_runtime.h>
#include <cuda_bf16.h>
#include <cstdint>

typedef unsigned long long u64;
typedef unsigned int u32;

#define KD 25088
#define KH 4096
#define NROI 2048
#define NOUT 25
#define NCLS_ 21
#define KSPLIT2 14
#define KPER2 (KD / KSPLIT2)      // 1792
#define K2CH (KPER2 / 32)         // 56
#define K1CH (KH / 32)            // 128

// ---- mma.sync m16n8k16 bf16 (sm_80+ PTX, assembles for compute_103) ----
__device__ __forceinline__ void mma_bf16(float& d0, float& d1, float& d2, float& d3,
                                         u32 a0, u32 a1, u32 a2, u32 a3,
                                         u32 b0, u32 b1) {
    asm volatile(
        "mma.sync.aligned.m16n8k16.row.col.f32.bf16.bf16.f32 "
        "{%0,%1,%2,%3}, {%4,%5,%6,%7}, {%8,%9}, {%0,%1,%2,%3};"
        : "+f"(d0), "+f"(d1), "+f"(d2), "+f"(d3)
        : "r"(a0), "r"(a1), "r"(a2), "r"(a3), "r"(b0), "r"(b1));
}

// fp32 pair (x=k even, y=k odd) -> hi/lo bf16x2 (x in low 16 bits)
__device__ __forceinline__ void cvt_split(float x, float y, u32& hi, u32& lo) {
    asm("cvt.rn.bf16x2.f32 %0, %1, %2;" : "=r"(hi) : "f"(y), "f"(x));
    float rx = x - __uint_as_float(hi << 16);
    float ry = y - __uint_as_float(hi & 0xFFFF0000u);
    asm("cvt.rn.bf16x2.f32 %0, %1, %2;" : "=r"(lo) : "f"(ry), "f"(rx));
}

// scratch
__device__ __align__(16) float g_M[NOUT * KD];                          // 2.5 MB
__device__ __align__(16) float g_p2[(size_t)KSPLIT2 * 16 * 128 * 32];   // 3.5 MB
__device__ float g_biasf[NOUT];
__device__ float g_score[NROI];
__device__ __align__(16) float g_boxes[NROI * 4];

// ---------------- fused bias ----------------
__global__ void k_bias(const float* __restrict__ b1, const float* __restrict__ Wc,
                       const float* __restrict__ bc, const float* __restrict__ Wr,
                       const float* __restrict__ br) {
    int c = blockIdx.x;
    int tid = threadIdx.x;
    const float* p = (c < NCLS_) ? (Wc + (size_t)c * KH) : (Wr + (size_t)(c - NCLS_) * KH);
    float s = 0.f;
    for (int h = tid; h < KH; h += 256) s += b1[h] * p[h];
    __shared__ float red[256];
    red[tid] = s;
    __syncthreads();
    for (int o = 128; o > 0; o >>= 1) {
        if (tid < o) red[tid] += red[tid + o];
        __syncthreads();
    }
    if (tid == 0) g_biasf[c] = red[0] + ((c < NCLS_) ? bc[c] : br[c - NCLS_]);
}

// ---------------- k1: M[c,d] = P @ W1 via HMMA, full K in-CTA ----------------
// grid 196 (d-tiles of 128), 256 thr = 8 warps. A = P [32pad(25) x 32k] pitch-17 u32 hi/lo,
// B = W1^T tile [128 d][16 hp] u32 hi/lo (transposed during conversion).
__global__ __launch_bounds__(256, 2) void k1_tensor(const float* __restrict__ W1,
                                                    const float* __restrict__ Wc,
                                                    const float* __restrict__ Wr) {
    __shared__ u32 sBhi[128][17], sBlo[128][17];   // W1^T [d][h-pair]
    __shared__ u32 sAhi[32][17],  sAlo[32][17];    // P [c][k-pair]
    int tid = threadIdx.x, w = tid >> 5, lane = tid & 31;
    int g = lane >> 2, t = lane & 3;
    int dbase = blockIdx.x * 128;

    // zero-pad A rows 25..31 once
    if (tid < 7 * 17) {
        sAhi[25 + tid / 17][tid % 17] = 0u;
        sAlo[25 + tid / 17][tid % 17] = 0u;
    }

    float acc[2][2][4];
#pragma unroll
    for (int mt = 0; mt < 2; mt++)
#pragma unroll
        for (int nt = 0; nt < 2; nt++)
#pragma unroll
            for (int j = 0; j < 4; j++) acc[mt][nt][j] = 0.f;

    int ac = tid >> 3, akq = tid & 7;
    const float* asrc = (tid < 200)
        ? ((ac < NCLS_) ? Wc + (size_t)ac * KH : Wr + (size_t)(ac - NCLS_) * KH) : Wc;

    float4 wv0[2], wv1[2], av;
    // prologue: load chunk 0
    {
#pragma unroll
        for (int i = 0; i < 2; i++) {
            int u = tid + 256 * i;
            int hp = u & 15, dq = u >> 4;
            const float* p = W1 + (size_t)(2 * hp) * KD + dbase + dq * 4;
            wv0[i] = *(const float4*)p;
            wv1[i] = *(const float4*)(p + KD);
        }
        if (tid < 200) av = *(const float4*)(asrc + akq * 4);
    }

    for (int ch = 0; ch < K1CH; ch++) {
        __syncthreads();
        // convert + store B (transpose) and A
#pragma unroll
        for (int i = 0; i < 2; i++) {
            int u = tid + 256 * i;
            int hp = u & 15, dq = u >> 4;
            const float* x0 = (const float*)&wv0[i];
            const float* x1 = (const float*)&wv1[i];
#pragma unroll
            for (int j = 0; j < 4; j++) {
                u32 hi, lo;
                cvt_split(x0[j], x1[j], hi, lo);
                sBhi[dq * 4 + j][hp] = hi;
                sBlo[dq * 4 + j][hp] = lo;
            }
        }
        if (tid < 200) {
            u32 h0, l0, h1, l1;
            cvt_split(av.x, av.y, h0, l0);
            cvt_split(av.z, av.w, h1, l1);
            sAhi[ac][akq * 2] = h0; sAhi[ac][akq * 2 + 1] = h1;
            sAlo[ac][akq * 2] = l0; sAlo[ac][akq * 2 + 1] = l1;
        }
        __syncthreads();
        // prefetch next chunk
        if (ch + 1 < K1CH) {
            int h0 = (ch + 1) * 32;
#pragma unroll
            for (int i = 0; i < 2; i++) {
                int u = tid + 256 * i;
                int hp = u & 15, dq = u >> 4;
                const float* p = W1 + (size_t)(h0 + 2 * hp) * KD + dbase + dq * 4;
                wv0[i] = *(const float4*)p;
                wv1[i] = *(const float4*)(p + KD);
            }
            if (tid < 200) av = *(const float4*)(asrc + h0 + akq * 4);
        }
        // compute: 2 k-steps x 2 m-tiles x 2 n-tiles x 3 splits
#pragma unroll
        for (int kk = 0; kk < 2; kk++) {
            int kp = kk * 8 + t;
            u32 ah[2][4], al[2][4];
#pragma unroll
            for (int mt = 0; mt < 2; mt++) {
                int r = mt * 16 + g;
                ah[mt][0] = sAhi[r][kp];     ah[mt][1] = sAhi[r + 8][kp];
                ah[mt][2] = sAhi[r][kp + 4]; ah[mt][3] = sAhi[r + 8][kp + 4];
                al[mt][0] = sAlo[r][kp];     al[mt][1] = sAlo[r + 8][kp];
                al[mt][2] = sAlo[r][kp + 4]; al[mt][3] = sAlo[r + 8][kp + 4];
            }
#pragma unroll
            for (int nt = 0; nt < 2; nt++) {
                int d = w * 16 + nt * 8 + g;
                u32 b0h = sBhi[d][kp], b1h = sBhi[d][kp + 4];
                u32 b0l = sBlo[d][kp], b1l = sBlo[d][kp + 4];
#pragma unroll
                for (int mt = 0; mt < 2; mt++) {
                    mma_bf16(acc[mt][nt][0], acc[mt][nt][1], acc[mt][nt][2], acc[mt][nt][3],
                             ah[mt][0], ah[mt][1], ah[mt][2], ah[mt][3], b0h, b1h);
                    mma_bf16(acc[mt][nt][0], acc[mt][nt][1], acc[mt][nt][2], acc[mt][nt][3],
                             ah[mt][0], ah[mt][1], ah[mt][2], ah[mt][3], b0l, b1l);
                    mma_bf16(acc[mt][nt][0], acc[mt][nt][1], acc[mt][nt][2], acc[mt][nt][3],
                             al[mt][0], al[mt][1], al[mt][2], al[mt][3], b0h, b1h);
                }
            }
        }
    }

    // epilogue: D fragment rows = c, cols = d
#pragma unroll
    for (int mt = 0; mt < 2; mt++) {
#pragma unroll
        for (int nt = 0; nt < 2; nt++) {
            int c0 = mt * 16 + g;
            int d0 = dbase + w * 16 + nt * 8 + t * 2;
            if (c0 < NOUT) {
                g_M[(size_t)c0 * KD + d0]     = acc[mt][nt][0];
                g_M[(size_t)c0 * KD + d0 + 1] = acc[mt][nt][1];
            }
            if (c0 + 8 < NOUT) {
                g_M[(size_t)(c0 + 8) * KD + d0]     = acc[mt][nt][2];
                g_M[(size_t)(c0 + 8) * KD + d0 + 1] = acc[mt][nt][3];
            }
        }
    }
}

// ---------------- k2: logits partials = feats @ M^T via HMMA ----------------
// grid (16 rowgroups, 14 k-splits), 256 thr = 8 warps. Warp = 16 rows x 32 c.
__global__ __launch_bounds__(256, 2) void k2_tensor(const float* __restrict__ feats) {
    __shared__ u32 sAhi[128][17], sAlo[128][17];   // feats [row][k-pair]
    __shared__ u32 sBhi[32][17],  sBlo[32][17];    // M [c pad32][k-pair]
    int tid = threadIdx.x, w = tid >> 5, lane = tid & 31;
    int g = lane >> 2, t = lane & 3;
    int rowbase = blockIdx.x * 128;
    int kstart = blockIdx.y * KPER2;

    if (tid < 7 * 17) {
        sBhi[25 + tid / 17][tid % 17] = 0u;
        sBlo[25 + tid / 17][tid % 17] = 0u;
    }

    float acc[4][4];
#pragma unroll
    for (int nt = 0; nt < 4; nt++)
#pragma unroll
        for (int j = 0; j < 4; j++) acc[nt][j] = 0.f;

    float4 fa[4], fb;
    {
#pragma unroll
        for (int i = 0; i < 4; i++) {
            int u = tid + 256 * i;
            fa[i] = *(const float4*)(feats + (size_t)(rowbase + (u >> 3)) * KD + kstart + (u & 7) * 4);
        }
        if (tid < 200)
            fb = *(const float4*)(g_M + (size_t)(tid >> 3) * KD + kstart + (tid & 7) * 4);
    }

    for (int ch = 0; ch < K2CH; ch++) {
        __syncthreads();
#pragma unroll
        for (int i = 0; i < 4; i++) {
            int u = tid + 256 * i, row = u >> 3, kq = u & 7;
            u32 h0, l0, h1, l1;
            cvt_split(fa[i].x, fa[i].y, h0, l0);
            cvt_split(fa[i].z, fa[i].w, h1, l1);
            sAhi[row][kq * 2] = h0; sAhi[row][kq * 2 + 1] = h1;
            sAlo[row][kq * 2] = l0; sAlo[row][kq * 2 + 1] = l1;
        }
        if (tid < 200) {
            int c = tid >> 3, kq = tid & 7;
            u32 h0, l0, h1, l1;
            cvt_split(fb.x, fb.y, h0, l0);
            cvt_split(fb.z, fb.w, h1, l1);
            sBhi[c][kq * 2] = h0; sBhi[c][kq * 2 + 1] = h1;
            sBlo[c][kq * 2] = l0; sBlo[c][kq * 2 + 1] = l1;
        }
        __syncthreads();
        if (ch + 1 < K2CH) {
            int k0 = kstart + (ch + 1) * 32;
#pragma unroll
            for (int i = 0; i < 4; i++) {
                int u = tid + 256 * i;
                fa[i] = *(const float4*)(feats + (size_t)(rowbase + (u >> 3)) * KD + k0 + (u & 7) * 4);
            }
            if (tid < 200)
                fb = *(const float4*)(g_M + (size_t)(tid >> 3) * KD + k0 + (tid & 7) * 4);
        }
#pragma unroll
        for (int kk = 0; kk < 2; kk++) {
            int kp = kk * 8 + t;
            int r0 = w * 16 + g;
            u32 a0h = sAhi[r0][kp],     a1h = sAhi[r0 + 8][kp];
            u32 a2h = sAhi[r0][kp + 4], a3h = sAhi[r0 + 8][kp + 4];
            u32 a0l = sAlo[r0][kp],     a1l = sAlo[r0 + 8][kp];
            u32 a2l = sAlo[r0][kp + 4], a3l = sAlo[r0 + 8][kp + 4];
#pragma unroll
            for (int nt = 0; nt < 4; nt++) {
                int n = nt * 8 + g;
                u32 b0h = sBhi[n][kp], b1h = sBhi[n][kp + 4];
                u32 b0l = sBlo[n][kp], b1l = sBlo[n][kp + 4];
                mma_bf16(acc[nt][0], acc[nt][1], acc[nt][2], acc[nt][3],
                         a0h, a1h, a2h, a3h, b0h, b1h);
                mma_bf16(acc[nt][0], acc[nt][1], acc[nt][2], acc[nt][3],
                         a0h, a1h, a2h, a3h, b0l, b1l);
                mma_bf16(acc[nt][0], acc[nt][1], acc[nt][2], acc[nt][3],
                         a0l, a1l, a2l, a3l, b0h, b1h);
            }
        }
    }

    float* gp = g_p2 + (size_t)(blockIdx.y * 16 + blockIdx.x) * 4096;
#pragma unroll
    for (int nt = 0; nt < 4; nt++) {
        int rl = w * 16 + g, c0 = nt * 8 + t * 2;
        gp[rl * 32 + c0]           = acc[nt][0];
        gp[rl * 32 + c0 + 1]       = acc[nt][1];
        gp[(rl + 8) * 32 + c0]     = acc[nt][2];
        gp[(rl + 8) * 32 + c0 + 1] = acc[nt][3];
    }
}

// ---------------- k2r: sum 14 seg partials + softmax/argmax/box decode ----------------
__global__ __launch_bounds__(256) void k2r(const float* __restrict__ props) {
    int tid = threadIdx.x, lane = tid & 31;
    int row = blockIdx.x * 8 + (tid >> 5);
    int rg = row >> 7, rl = row & 127;

    float t[NOUT];
#pragma unroll
    for (int c = 0; c < NOUT; c++) t[c] = 0.f;
    if (lane < KSPLIT2) {
        const float* base = g_p2 + (size_t)(lane * 16 + rg) * 4096 + rl * 32;
#pragma unroll
        for (int c = 0; c < NOUT; c++) t[c] = base[c];
    }
#pragma unroll
    for (int c = 0; c < NOUT; c++) {
#pragma unroll
        for (int o = 16; o > 0; o >>= 1) t[c] += __shfl_xor_sync(0xffffffffu, t[c], o);
    }

    if (lane == 0) {
#pragma unroll
        for (int c = 0; c < NOUT; c++) t[c] += g_biasf[c];
        float m = t[0]; int idx = 0;
#pragma unroll
        for (int c = 1; c < NCLS_; c++) { if (t[c] > m) { m = t[c]; idx = c; } }
        float ssum = 0.f;
#pragma unroll
        for (int c = 0; c < NCLS_; c++) ssum += expf(t[c] - m);
        float score = 1.f / ssum;
        bool valid = (idx != 0) && (score >= 0.01f);
        float p0 = props[row * 4 + 0], p1 = props[row * 4 + 1];
        float p2 = props[row * 4 + 2], p3 = props[row * 4 + 3];
        g_score[row] = valid ? score : 0.f;
        g_boxes[row * 4 + 0] = p0 + p2 * t[NCLS_ + 0];
        g_boxes[row * 4 + 1] = p1 + p3 * t[NCLS_ + 1];
        g_boxes[row * 4 + 2] = p2 * expf(t[NCLS_ + 2]);
        g_boxes[row * 4 + 3] = p3 * expf(t[NCLS_ + 3]);
    }
}

// ---------------- k3: exact greedy NMS per batch ----------------
__global__ __launch_bounds__(512) void k3_nms(float* __restrict__ out) {
    __shared__ float sraw[512];
    __shared__ float ss[512], sx0[512], sy0[512], sx1[512], sy1[512], sa[512];
    __shared__ short sord[512];
    __shared__ unsigned char ssup[512];

    int b = blockIdx.x, t = threadIdx.x;
    int gi = b * 512 + t;
    float sc = g_score[gi];
    sraw[t] = sc;
    float bx = g_boxes[gi * 4 + 0], by = g_boxes[gi * 4 + 1];
    float bw = g_boxes[gi * 4 + 2], bh = g_boxes[gi * 4 + 3];
    __syncthreads();

    int r = 0;
    for (int i = 0; i < 512; i++) {
        float si = sraw[i];
        r += (si > sc) || (si == sc && i < t);
    }

    float x0 = fminf(fmaxf(bx, 0.f), 599.f);
    float y0 = fminf(fmaxf(by, 0.f), 599.f);
    float x1 = fminf(fmaxf(bx + bw - 1.f, 0.f), 599.f);
    float y1 = fminf(fmaxf(by + bh - 1.f, 0.f), 599.f);
    float area = fmaxf(x1 - x0 + 1.f, 0.f) * fmaxf(y1 - y0 + 1.f, 0.f);

    ss[r] = sc; sx0[r] = x0; sy0[r] = y0; sx1[r] = x1; sy1[r] = y1; sa[r] = area;
    sord[r] = (short)t;
    ssup[t] = 0;
    __syncthreads();

    for (int i = 0; i < 512; i++) {
        bool alive = (!ssup[i]) && (ss[i] > 0.f);
        if (alive && t != i) {
            float ix0 = fmaxf(sx0[i], sx0[t]);
            float iy0 = fmaxf(sy0[i], sy0[t]);
            float ix1 = fminf(sx1[i], sx1[t]);
            float iy1 = fminf(sy1[i], sy1[t]);
            float inter = fmaxf(ix1 - ix0 + 1.f, 0.f) * fmaxf(iy1 - iy0 + 1.f, 0.f);
            float iou = inter / (sa[i] + sa[t] - inter + 1e-9f);
            if (iou > 0.5f) ssup[t] = 1;
        }
        __syncthreads();
    }

    bool keep = (!ssup[t]) && (ss[t] > 0.f);
    int orig = sord[t];
    int go = b * 512 + orig;

    out[go] = keep ? ss[t] : 0.f;

    float obx = g_boxes[go * 4 + 0], oby = g_boxes[go * 4 + 1];
    float obw = g_boxes[go * 4 + 2], obh = g_boxes[go * 4 + 3];
    float* ob = out + NROI + (size_t)go * 4;
    if (keep) {
        ob[0] = obx; ob[1] = oby;
        ob[2] = obx + obw - 1.f;
        ob[3] = oby + obh - 1.f;
    } else {
        ob[0] = 0.f; ob[1] = 0.f; ob[2] = -1.f; ob[3] = -1.f;
    }
}

extern "C" void kernel_launch(void* const* d_in, const int* in_sizes, int n_in,
                              void* d_out, int out_size) {
    (void)in_sizes; (void)n_in; (void)out_size;
    const float* rois  = (const float*)d_in[0];
    const float* props = (const float*)d_in[1];
    const float* W1    = (const float*)d_in[2];
    const float* b1    = (const float*)d_in[3];
    const float* Wc    = (const float*)d_in[4];
    const float* bc    = (const float*)d_in[5];
    const float* Wr    = (const float*)d_in[6];
    const float* br    = (const float*)d_in[7];
    float* out = (float*)d_out;

    k_bias<<<NOUT, 256>>>(b1, Wc, bc, Wr, br);
    k1_tensor<<<KD / 128, 256>>>(W1, Wc, Wr);              // 196 CTAs
    k2_tensor<<<dim3(16, KSPLIT2), 256>>>(rois);           // 224 CTAs
    k2r<<<NROI / 8, 256>>>(props);
    k3_nms<<<4, 512>>>(out);
}

// round 10
// speedup vs baseline: 1.3350x; 1.3350x over previous
#include <cuda_runtime.h>
#include <cuda_bf16.h>
#include <cstdint>

typedef unsigned long long u64;
typedef unsigned int u32;

#define KD 25088
#define KH 4096
#define NROI 2048
#define NOUT 25
#define NCLS_ 21
#define KSPLIT2 14
#define KPER2 (KD / KSPLIT2)      // 1792
#define K2CH (KPER2 / 32)         // 56
#define K1CH (KH / 32)            // 128

// ---- mma.sync m16n8k16 bf16 (sm_80+ PTX path; validated R9, rel_err 2e-5) ----
__device__ __forceinline__ void mma_bf16(float& d0, float& d1, float& d2, float& d3,
                                         u32 a0, u32 a1, u32 a2, u32 a3,
                                         u32 b0, u32 b1) {
    asm volatile(
        "mma.sync.aligned.m16n8k16.row.col.f32.bf16.bf16.f32 "
        "{%0,%1,%2,%3}, {%4,%5,%6,%7}, {%8,%9}, {%0,%1,%2,%3};"
        : "+f"(d0), "+f"(d1), "+f"(d2), "+f"(d3)
        : "r"(a0), "r"(a1), "r"(a2), "r"(a3), "r"(b0), "r"(b1));
}

// fp32 pair (x -> low 16, y -> high 16) hi/lo split
__device__ __forceinline__ void cvt_split(float x, float y, u32& hi, u32& lo) {
    asm("cvt.rn.bf16x2.f32 %0, %1, %2;" : "=r"(hi) : "f"(y), "f"(x));
    float rx = x - __uint_as_float(hi << 16);
    float ry = y - __uint_as_float(hi & 0xFFFF0000u);
    asm("cvt.rn.bf16x2.f32 %0, %1, %2;" : "=r"(lo) : "f"(ry), "f"(rx));
}

// scratch
__device__ __align__(16) float g_M[NOUT * KD];                          // 2.5 MB
__device__ __align__(16) float g_p2[(size_t)KSPLIT2 * 16 * 128 * 32];   // 3.5 MB
__device__ float g_biasf[NOUT];
__device__ float g_score[NROI];
__device__ __align__(16) float g_boxes[NROI * 4];

__global__ void k_dummy() {}

// ---------------- fused bias ----------------
__global__ void k_bias(const float* __restrict__ b1, const float* __restrict__ Wc,
                       const float* __restrict__ bc, const float* __restrict__ Wr,
                       const float* __restrict__ br) {
    int c = blockIdx.x;
    int tid = threadIdx.x;
    const float* p = (c < NCLS_) ? (Wc + (size_t)c * KH) : (Wr + (size_t)(c - NCLS_) * KH);
    float s = 0.f;
    for (int h = tid; h < KH; h += 256) s += b1[h] * p[h];
    __shared__ float red[256];
    red[tid] = s;
    __syncthreads();
    for (int o = 128; o > 0; o >>= 1) {
        if (tid < o) red[tid] += red[tid + o];
        __syncthreads();
    }
    if (tid == 0) g_biasf[c] = red[0] + ((c < NCLS_) ? bc[c] : br[c - NCLS_]);
}

// ---------------- k1: M[c,d] = P @ W1 via HMMA, full K in-CTA ----------------
// grid 196 (d-tiles of 128), 256 thr = 8 warps.
// B tile layout [kp 16][d 128] pitch 132: warp-contiguous LDG (512B/row) + STS.128.
// A = P [32pad(25)][kp 16] pitch 17.
__global__ __launch_bounds__(256, 2) void k1_tensor(const float* __restrict__ W1,
                                                    const float* __restrict__ Wc,
                                                    const float* __restrict__ Wr) {
    __shared__ u32 sBhi[16][132], sBlo[16][132];   // [k-pair][d]
    __shared__ u32 sAhi[32][17],  sAlo[32][17];    // [c][k-pair]
    int tid = threadIdx.x, w = tid >> 5, lane = tid & 31;
    int g = lane >> 2, t = lane & 3;
    int dbase = blockIdx.x * 128;

    if (tid < 7 * 17) {       // zero-pad A rows 25..31
        sAhi[25 + tid / 17][tid % 17] = 0u;
        sAlo[25 + tid / 17][tid % 17] = 0u;
    }

    float acc[2][2][4];
#pragma unroll
    for (int mt = 0; mt < 2; mt++)
#pragma unroll
        for (int nt = 0; nt < 2; nt++)
#pragma unroll
            for (int j = 0; j < 4; j++) acc[mt][nt][j] = 0.f;

    int ac = tid >> 3, akq = tid & 7;
    const float* asrc = (tid < 200)
        ? ((ac < NCLS_) ? Wc + (size_t)ac * KH : Wr + (size_t)(ac - NCLS_) * KH) : Wc;

    // staging geometry: u = tid + 256*i; rp = u>>5 (k-pair row), f4 = u&31 (d/4)
    float4 wv0[2], wv1[2], av;
    {
#pragma unroll
        for (int i = 0; i < 2; i++) {
            int u = tid + 256 * i;
            int rp = u >> 5, f4 = u & 31;
            const float* p = W1 + (size_t)(2 * rp) * KD + dbase + 4 * f4;
            wv0[i] = *(const float4*)p;
            wv1[i] = *(const float4*)(p + KD);
        }
        if (tid < 200) av = *(const float4*)(asrc + akq * 4);
    }

    for (int ch = 0; ch < K1CH; ch++) {
        __syncthreads();
        // convert + store B (STS.128, conflict-free) and A
#pragma unroll
        for (int i = 0; i < 2; i++) {
            int u = tid + 256 * i;
            int rp = u >> 5, f4 = u & 31;
            const float* x0 = (const float*)&wv0[i];
            const float* x1 = (const float*)&wv1[i];
            u32 hi[4], lo[4];
#pragma unroll
            for (int j = 0; j < 4; j++) cvt_split(x0[j], x1[j], hi[j], lo[j]);
            *(uint4*)&sBhi[rp][4 * f4] = make_uint4(hi[0], hi[1], hi[2], hi[3]);
            *(uint4*)&sBlo[rp][4 * f4] = make_uint4(lo[0], lo[1], lo[2], lo[3]);
        }
        if (tid < 200) {
            u32 h0, l0, h1, l1;
            cvt_split(av.x, av.y, h0, l0);
            cvt_split(av.z, av.w, h1, l1);
            sAhi[ac][akq * 2] = h0; sAhi[ac][akq * 2 + 1] = h1;
            sAlo[ac][akq * 2] = l0; sAlo[ac][akq * 2 + 1] = l1;
        }
        __syncthreads();
        // prefetch next chunk
        if (ch + 1 < K1CH) {
            int h0 = (ch + 1) * 32;
#pragma unroll
            for (int i = 0; i < 2; i++) {
                int u = tid + 256 * i;
                int rp = u >> 5, f4 = u & 31;
                const float* p = W1 + (size_t)(h0 + 2 * rp) * KD + dbase + 4 * f4;
                wv0[i] = *(const float4*)p;
                wv1[i] = *(const float4*)(p + KD);
            }
            if (tid < 200) av = *(const float4*)(asrc + h0 + akq * 4);
        }
        // compute: 2 k-steps; split-outer => 4 independent chains between dependent MMAs
#pragma unroll
        for (int kk = 0; kk < 2; kk++) {
            int kp = kk * 8 + t;
            u32 ah[2][4], al[2][4];
#pragma unroll
            for (int mt = 0; mt < 2; mt++) {
                int r = mt * 16 + g;
                ah[mt][0] = sAhi[r][kp];     ah[mt][1] = sAhi[r + 8][kp];
                ah[mt][2] = sAhi[r][kp + 4]; ah[mt][3] = sAhi[r + 8][kp + 4];
                al[mt][0] = sAlo[r][kp];     al[mt][1] = sAlo[r + 8][kp];
                al[mt][2] = sAlo[r][kp + 4]; al[mt][3] = sAlo[r + 8][kp + 4];
            }
            u32 bh0[2], bh1[2], bl0[2], bl1[2];
#pragma unroll
            for (int nt = 0; nt < 2; nt++) {
                int d = w * 16 + nt * 8 + g;
                bh0[nt] = sBhi[kp][d]; bh1[nt] = sBhi[kp + 4][d];
                bl0[nt] = sBlo[kp][d]; bl1[nt] = sBlo[kp + 4][d];
            }
#pragma unroll
            for (int nt = 0; nt < 2; nt++)
#pragma unroll
                for (int mt = 0; mt < 2; mt++)
                    mma_bf16(acc[mt][nt][0], acc[mt][nt][1], acc[mt][nt][2], acc[mt][nt][3],
                             ah[mt][0], ah[mt][1], ah[mt][2], ah[mt][3], bh0[nt], bh1[nt]);
#pragma unroll
            for (int nt = 0; nt < 2; nt++)
#pragma unroll
                for (int mt = 0; mt < 2; mt++)
                    mma_bf16(acc[mt][nt][0], acc[mt][nt][1], acc[mt][nt][2], acc[mt][nt][3],
                             ah[mt][0], ah[mt][1], ah[mt][2], ah[mt][3], bl0[nt], bl1[nt]);
#pragma unroll
            for (int nt = 0; nt < 2; nt++)
#pragma unroll
                for (int mt = 0; mt < 2; mt++)
                    mma_bf16(acc[mt][nt][0], acc[mt][nt][1], acc[mt][nt][2], acc[mt][nt][3],
                             al[mt][0], al[mt][1], al[mt][2], al[mt][3], bh0[nt], bh1[nt]);
        }
    }

    // epilogue
#pragma unroll
    for (int mt = 0; mt < 2; mt++) {
#pragma unroll
        for (int nt = 0; nt < 2; nt++) {
            int c0 = mt * 16 + g;
            int d0 = dbase + w * 16 + nt * 8 + t * 2;
            if (c0 < NOUT) {
                g_M[(size_t)c0 * KD + d0]     = acc[mt][nt][0];
                g_M[(size_t)c0 * KD + d0 + 1] = acc[mt][nt][1];
            }
            if (c0 + 8 < NOUT) {
                g_M[(size_t)(c0 + 8) * KD + d0]     = acc[mt][nt][2];
                g_M[(size_t)(c0 + 8) * KD + d0 + 1] = acc[mt][nt][3];
            }
        }
    }
}

// ---------------- k2: logits partials = feats @ M^T via HMMA ----------------
__global__ __launch_bounds__(256, 2) void k2_tensor(const float* __restrict__ feats) {
    __shared__ u32 sAhi[128][17], sAlo[128][17];   // feats [row][k-pair]
    __shared__ u32 sBhi[32][17],  sBlo[32][17];    // M [c pad32][k-pair]
    int tid = threadIdx.x, w = tid >> 5, lane = tid & 31;
    int g = lane >> 2, t = lane & 3;
    int rowbase = blockIdx.x * 128;
    int kstart = blockIdx.y * KPER2;

    if (tid < 7 * 17) {
        sBhi[25 + tid / 17][tid % 17] = 0u;
        sBlo[25 + tid / 17][tid % 17] = 0u;
    }

    float acc[4][4];
#pragma unroll
    for (int nt = 0; nt < 4; nt++)
#pragma unroll
        for (int j = 0; j < 4; j++) acc[nt][j] = 0.f;

    float4 fa[4], fb;
    {
#pragma unroll
        for (int i = 0; i < 4; i++) {
            int u = tid + 256 * i;
            fa[i] = *(const float4*)(feats + (size_t)(rowbase + (u >> 3)) * KD + kstart + (u & 7) * 4);
        }
        if (tid < 200)
            fb = *(const float4*)(g_M + (size_t)(tid >> 3) * KD + kstart + (tid & 7) * 4);
    }

    for (int ch = 0; ch < K2CH; ch++) {
        __syncthreads();
#pragma unroll
        for (int i = 0; i < 4; i++) {
            int u = tid + 256 * i, row = u >> 3, kq = u & 7;
            u32 h0, l0, h1, l1;
            cvt_split(fa[i].x, fa[i].y, h0, l0);
            cvt_split(fa[i].z, fa[i].w, h1, l1);
            sAhi[row][kq * 2] = h0; sAhi[row][kq * 2 + 1] = h1;
            sAlo[row][kq * 2] = l0; sAlo[row][kq * 2 + 1] = l1;
        }
        if (tid < 200) {
            int c = tid >> 3, kq = tid & 7;
            u32 h0, l0, h1, l1;
            cvt_split(fb.x, fb.y, h0, l0);
            cvt_split(fb.z, fb.w, h1, l1);
            sBhi[c][kq * 2] = h0; sBhi[c][kq * 2 + 1] = h1;
            sBlo[c][kq * 2] = l0; sBlo[c][kq * 2 + 1] = l1;
        }
        __syncthreads();
        if (ch + 1 < K2CH) {
            int k0 = kstart + (ch + 1) * 32;
#pragma unroll
            for (int i = 0; i < 4; i++) {
                int u = tid + 256 * i;
                fa[i] = *(const float4*)(feats + (size_t)(rowbase + (u >> 3)) * KD + k0 + (u & 7) * 4);
            }
            if (tid < 200)
                fb = *(const float4*)(g_M + (size_t)(tid >> 3) * KD + k0 + (tid & 7) * 4);
        }
#pragma unroll
        for (int kk = 0; kk < 2; kk++) {
            int kp = kk * 8 + t;
            int r0 = w * 16 + g;
            u32 a0h = sAhi[r0][kp],     a1h = sAhi[r0 + 8][kp];
            u32 a2h = sAhi[r0][kp + 4], a3h = sAhi[r0 + 8][kp + 4];
            u32 a0l = sAlo[r0][kp],     a1l = sAlo[r0 + 8][kp];
            u32 a2l = sAlo[r0][kp + 4], a3l = sAlo[r0 + 8][kp + 4];
            u32 bh0[4], bh1[4], bl0[4], bl1[4];
#pragma unroll
            for (int nt = 0; nt < 4; nt++) {
                int n = nt * 8 + g;
                bh0[nt] = sBhi[n][kp]; bh1[nt] = sBhi[n][kp + 4];
                bl0[nt] = sBlo[n][kp]; bl1[nt] = sBlo[n][kp + 4];
            }
#pragma unroll
            for (int nt = 0; nt < 4; nt++)
                mma_bf16(acc[nt][0], acc[nt][1], acc[nt][2], acc[nt][3],
                         a0h, a1h, a2h, a3h, bh0[nt], bh1[nt]);
#pragma unroll
            for (int nt = 0; nt < 4; nt++)
                mma_bf16(acc[nt][0], acc[nt][1], acc[nt][2], acc[nt][3],
                         a0h, a1h, a2h, a3h, bl0[nt], bl1[nt]);
#pragma unroll
            for (int nt = 0; nt < 4; nt++)
                mma_bf16(acc[nt][0], acc[nt][1], acc[nt][2], acc[nt][3],
                         a0l, a1l, a2l, a3l, bh0[nt], bh1[nt]);
        }
    }

    float* gp = g_p2 + (size_t)(blockIdx.y * 16 + blockIdx.x) * 4096;
#pragma unroll
    for (int nt = 0; nt < 4; nt++) {
        int rl = w * 16 + g, c0 = nt * 8 + t * 2;
        gp[rl * 32 + c0]           = acc[nt][0];
        gp[rl * 32 + c0 + 1]       = acc[nt][1];
        gp[(rl + 8) * 32 + c0]     = acc[nt][2];
        gp[(rl + 8) * 32 + c0 + 1] = acc[nt][3];
    }
}

// ---------------- k2r: sum 14 seg partials + softmax/argmax/box decode ----------------
__global__ __launch_bounds__(256) void k2r(const float* __restrict__ props) {
    int tid = threadIdx.x, lane = tid & 31;
    int row = blockIdx.x * 8 + (tid >> 5);
    int rg = row >> 7, rl = row & 127;

    float t[NOUT];
#pragma unroll
    for (int c = 0; c < NOUT; c++) t[c] = 0.f;
    if (lane < KSPLIT2) {
        const float* base = g_p2 + (size_t)(lane * 16 + rg) * 4096 + rl * 32;
#pragma unroll
        for (int c = 0; c < NOUT; c++) t[c] = base[c];
    }
#pragma unroll
    for (int c = 0; c < NOUT; c++) {
#pragma unroll
        for (int o = 16; o > 0; o >>= 1) t[c] += __shfl_xor_sync(0xffffffffu, t[c], o);
    }

    if (lane == 0) {
#pragma unroll
        for (int c = 0; c < NOUT; c++) t[c] += g_biasf[c];
        float m = t[0]; int idx = 0;
#pragma unroll
        for (int c = 1; c < NCLS_; c++) { if (t[c] > m) { m = t[c]; idx = c; } }
        float ssum = 0.f;
#pragma unroll
        for (int c = 0; c < NCLS_; c++) ssum += expf(t[c] - m);
        float score = 1.f / ssum;
        bool valid = (idx != 0) && (score >= 0.01f);
        float p0 = props[row * 4 + 0], p1 = props[row * 4 + 1];
        float p2 = props[row * 4 + 2], p3 = props[row * 4 + 3];
        g_score[row] = valid ? score : 0.f;
        g_boxes[row * 4 + 0] = p0 + p2 * t[NCLS_ + 0];
        g_boxes[row * 4 + 1] = p1 + p3 * t[NCLS_ + 1];
        g_boxes[row * 4 + 2] = p2 * expf(t[NCLS_ + 2]);
        g_boxes[row * 4 + 3] = p3 * expf(t[NCLS_ + 3]);
    }
}

// ---------------- k3: exact greedy NMS per batch ----------------
__global__ __launch_bounds__(512) void k3_nms(float* __restrict__ out) {
    __shared__ float sraw[512];
    __shared__ float ss[512], sx0[512], sy0[512], sx1[512], sy1[512], sa[512];
    __shared__ short sord[512];
    __shared__ unsigned char ssup[512];

    int b = blockIdx.x, t = threadIdx.x;
    int gi = b * 512 + t;
    float sc = g_score[gi];
    sraw[t] = sc;
    float bx = g_boxes[gi * 4 + 0], by = g_boxes[gi * 4 + 1];
    float bw = g_boxes[gi * 4 + 2], bh = g_boxes[gi * 4 + 3];
    __syncthreads();

    int r = 0;
    for (int i = 0; i < 512; i++) {
        float si = sraw[i];
        r += (si > sc) || (si == sc && i < t);
    }

    float x0 = fminf(fmaxf(bx, 0.f), 599.f);
    float y0 = fminf(fmaxf(by, 0.f), 599.f);
    float x1 = fminf(fmaxf(bx + bw - 1.f, 0.f), 599.f);
    float y1 = fminf(fmaxf(by + bh - 1.f, 0.f), 599.f);
    float area = fmaxf(x1 - x0 + 1.f, 0.f) * fmaxf(y1 - y0 + 1.f, 0.f);

    ss[r] = sc; sx0[r] = x0; sy0[r] = y0; sx1[r] = x1; sy1[r] = y1; sa[r] = area;
    sord[r] = (short)t;
    ssup[t] = 0;
    __syncthreads();

    for (int i = 0; i < 512; i++) {
        bool alive = (!ssup[i]) && (ss[i] > 0.f);
        if (alive && t != i) {
            float ix0 = fmaxf(sx0[i], sx0[t]);
            float iy0 = fmaxf(sy0[i], sy0[t]);
            float ix1 = fminf(sx1[i], sx1[t]);
            float iy1 = fminf(sy1[i], sy1[t]);
            float inter = fmaxf(ix1 - ix0 + 1.f, 0.f) * fmaxf(iy1 - iy0 + 1.f, 0.f);
            float iou = inter / (sa[i] + sa[t] - inter + 1e-9f);
            if (iou > 0.5f) ssup[t] = 1;
        }
        __syncthreads();
    }

    bool keep = (!ssup[t]) && (ss[t] > 0.f);
    int orig = sord[t];
    int go = b * 512 + orig;

    out[go] = keep ? ss[t] : 0.f;

    float obx = g_boxes[go * 4 + 0], oby = g_boxes[go * 4 + 1];
    float obw = g_boxes[go * 4 + 2], obh = g_boxes[go * 4 + 3];
    float* ob = out + NROI + (size_t)go * 4;
    if (keep) {
        ob[0] = obx; ob[1] = oby;
        ob[2] = obx + obw - 1.f;
        ob[3] = oby + obh - 1.f;
    } else {
        ob[0] = 0.f; ob[1] = 0.f; ob[2] = -1.f; ob[3] = -1.f;
    }
}

extern "C" void kernel_launch(void* const* d_in, const int* in_sizes, int n_in,
                              void* d_out, int out_size) {
    (void)in_sizes; (void)n_in; (void)out_size;
    const float* rois  = (const float*)d_in[0];
    const float* props = (const float*)d_in[1];
    const float* W1    = (const float*)d_in[2];
    const float* b1    = (const float*)d_in[3];
    const float* Wc    = (const float*)d_in[4];
    const float* bc    = (const float*)d_in[5];
    const float* Wr    = (const float*)d_in[6];
    const float* br    = (const float*)d_in[7];
    float* out = (float*)d_out;

    k_bias<<<NOUT, 256>>>(b1, Wc, bc, Wr, br);     // launch 1
    k_dummy<<<1, 32>>>();                          // launch 2 (profiler alignment)
    k_dummy<<<1, 32>>>();                          // launch 3
    k1_tensor<<<KD / 128, 256>>>(W1, Wc, Wr);      // launch 4 -> ncu captures this
    k2_tensor<<<dim3(16, KSPLIT2), 256>>>(rois);   // launch 5
    k2r<<<NROI / 8, 256>>>(props);                 // launch 6
    k3_nms<<<4, 512>>>(out);                       // launch 7
}

// round 12
// speedup vs baseline: 1.5186x; 1.1375x over previous
#include <cuda_runtime.h>
#include <cuda_bf16.h>
#include <cstdint>

typedef unsigned long long u64;
typedef unsigned int u32;

#define KD 25088
#define KH 4096
#define NROI 2048
#define NOUT 25
#define NCLS_ 21
#define KSPLIT2 28
#define KPER2 (KD / KSPLIT2)      // 896
#define K2CH (KPER2 / 32)         // 28
#define HSPL 2
#define KHPER (KH / HSPL)         // 2048
#define K1CH (KHPER / 32)         // 64

// ---- mma.sync m16n8k16 bf16 (validated R9/R10, rel_err 2e-5) ----
__device__ __forceinline__ void mma_bf16(float& d0, float& d1, float& d2, float& d3,
                                         u32 a0, u32 a1, u32 a2, u32 a3,
                                         u32 b0, u32 b1) {
    asm volatile(
        "mma.sync.aligned.m16n8k16.row.col.f32.bf16.bf16.f32 "
        "{%0,%1,%2,%3}, {%4,%5,%6,%7}, {%8,%9}, {%0,%1,%2,%3};"
        : "+f"(d0), "+f"(d1), "+f"(d2), "+f"(d3)
        : "r"(a0), "r"(a1), "r"(a2), "r"(a3), "r"(b0), "r"(b1));
}

__device__ __forceinline__ void cvt_split(float x, float y, u32& hi, u32& lo) {
    asm("cvt.rn.bf16x2.f32 %0, %1, %2;" : "=r"(hi) : "f"(y), "f"(x));
    float rx = x - __uint_as_float(hi << 16);
    float ry = y - __uint_as_float(hi & 0xFFFF0000u);
    asm("cvt.rn.bf16x2.f32 %0, %1, %2;" : "=r"(lo) : "f"(ry), "f"(rx));
}

// scratch
__device__ __align__(16) float g_Mpart[HSPL][NOUT * KD];                // 5 MB
__device__ __align__(16) float g_M[NOUT * KD];                          // 2.5 MB
__device__ __align__(16) float g_p2[(size_t)KSPLIT2 * 16 * 128 * 32];   // 7 MB
__device__ float g_biasf[NOUT];
__device__ float g_score[NROI];
__device__ __align__(16) float g_boxes[NROI * 4];

// ---------------- fused bias ----------------
__global__ void k_bias(const float* __restrict__ b1, const float* __restrict__ Wc,
                       const float* __restrict__ bc, const float* __restrict__ Wr,
                       const float* __restrict__ br) {
    int c = blockIdx.x;
    int tid = threadIdx.x;
    const float* p = (c < NCLS_) ? (Wc + (size_t)c * KH) : (Wr + (size_t)(c - NCLS_) * KH);
    float s = 0.f;
    for (int h = tid; h < KH; h += 256) s += b1[h] * p[h];
    __shared__ float red[256];
    red[tid] = s;
    __syncthreads();
    for (int o = 128; o > 0; o >>= 1) {
        if (tid < o) red[tid] += red[tid + o];
        __syncthreads();
    }
    if (tid == 0) g_biasf[c] = red[0] + ((c < NCLS_) ? bc[c] : br[c - NCLS_]);
}

// ---------------- k1: M partial = P @ W1 (h-range) via HMMA ----------------
// grid (196, HSPL), 256 thr. Identical fragment math to R10; h-split for 2x occupancy.
__global__ __launch_bounds__(256, 2) void k1_tensor(const float* __restrict__ W1,
                                                    const float* __restrict__ Wc,
                                                    const float* __restrict__ Wr) {
    __shared__ u32 sBhi[16][132], sBlo[16][132];   // [k-pair][d]
    __shared__ u32 sAhi[32][17],  sAlo[32][17];    // [c][k-pair]
    int tid = threadIdx.x, w = tid >> 5, lane = tid & 31;
    int g = lane >> 2, t = lane & 3;
    int dbase = blockIdx.x * 128;
    int hbase = blockIdx.y * KHPER;

    if (tid < 7 * 17) {
        sAhi[25 + tid / 17][tid % 17] = 0u;
        sAlo[25 + tid / 17][tid % 17] = 0u;
    }

    float acc[2][2][4];
#pragma unroll
    for (int mt = 0; mt < 2; mt++)
#pragma unroll
        for (int nt = 0; nt < 2; nt++)
#pragma unroll
            for (int j = 0; j < 4; j++) acc[mt][nt][j] = 0.f;

    int ac = tid >> 3, akq = tid & 7;
    const float* asrc = (tid < 200)
        ? ((ac < NCLS_) ? Wc + (size_t)ac * KH : Wr + (size_t)(ac - NCLS_) * KH) : Wc;

    float4 wv0[2], wv1[2], av;
    {
#pragma unroll
        for (int i = 0; i < 2; i++) {
            int u = tid + 256 * i;
            int rp = u >> 5, f4 = u & 31;
            const float* p = W1 + (size_t)(hbase + 2 * rp) * KD + dbase + 4 * f4;
            wv0[i] = *(const float4*)p;
            wv1[i] = *(const float4*)(p + KD);
        }
        if (tid < 200) av = *(const float4*)(asrc + hbase + akq * 4);
    }

    for (int ch = 0; ch < K1CH; ch++) {
        __syncthreads();
#pragma unroll
        for (int i = 0; i < 2; i++) {
            int u = tid + 256 * i;
            int rp = u >> 5, f4 = u & 31;
            const float* x0 = (const float*)&wv0[i];
            const float* x1 = (const float*)&wv1[i];
            u32 hi[4], lo[4];
#pragma unroll
            for (int j = 0; j < 4; j++) cvt_split(x0[j], x1[j], hi[j], lo[j]);
            *(uint4*)&sBhi[rp][4 * f4] = make_uint4(hi[0], hi[1], hi[2], hi[3]);
            *(uint4*)&sBlo[rp][4 * f4] = make_uint4(lo[0], lo[1], lo[2], lo[3]);
        }
        if (tid < 200) {
            u32 h0, l0, h1, l1;
            cvt_split(av.x, av.y, h0, l0);
            cvt_split(av.z, av.w, h1, l1);
            sAhi[ac][akq * 2] = h0; sAhi[ac][akq * 2 + 1] = h1;
            sAlo[ac][akq * 2] = l0; sAlo[ac][akq * 2 + 1] = l1;
        }
        __syncthreads();
        if (ch + 1 < K1CH) {
            int h0 = hbase + (ch + 1) * 32;
#pragma unroll
            for (int i = 0; i < 2; i++) {
                int u = tid + 256 * i;
                int rp = u >> 5, f4 = u & 31;
                const float* p = W1 + (size_t)(h0 + 2 * rp) * KD + dbase + 4 * f4;
                wv0[i] = *(const float4*)p;
                wv1[i] = *(const float4*)(p + KD);
            }
            if (tid < 200) av = *(const float4*)(asrc + h0 + akq * 4);
        }
#pragma unroll
        for (int kk = 0; kk < 2; kk++) {
            int kp = kk * 8 + t;
            u32 ah[2][4], al[2][4];
#pragma unroll
            for (int mt = 0; mt < 2; mt++) {
                int r = mt * 16 + g;
                ah[mt][0] = sAhi[r][kp];     ah[mt][1] = sAhi[r + 8][kp];
                ah[mt][2] = sAhi[r][kp + 4]; ah[mt][3] = sAhi[r + 8][kp + 4];
                al[mt][0] = sAlo[r][kp];     al[mt][1] = sAlo[r + 8][kp];
                al[mt][2] = sAlo[r][kp + 4]; al[mt][3] = sAlo[r + 8][kp + 4];
            }
            u32 bh0[2], bh1[2], bl0[2], bl1[2];
#pragma unroll
            for (int nt = 0; nt < 2; nt++) {
                int d = w * 16 + nt * 8 + g;
                bh0[nt] = sBhi[kp][d]; bh1[nt] = sBhi[kp + 4][d];
                bl0[nt] = sBlo[kp][d]; bl1[nt] = sBlo[kp + 4][d];
            }
#pragma unroll
            for (int nt = 0; nt < 2; nt++)
#pragma unroll
                for (int mt = 0; mt < 2; mt++)
                    mma_bf16(acc[mt][nt][0], acc[mt][nt][1], acc[mt][nt][2], acc[mt][nt][3],
                             ah[mt][0], ah[mt][1], ah[mt][2], ah[mt][3], bh0[nt], bh1[nt]);
#pragma unroll
            for (int nt = 0; nt < 2; nt++)
#pragma unroll
                for (int mt = 0; mt < 2; mt++)
                    mma_bf16(acc[mt][nt][0], acc[mt][nt][1], acc[mt][nt][2], acc[mt][nt][3],
                             ah[mt][0], ah[mt][1], ah[mt][2], ah[mt][3], bl0[nt], bl1[nt]);
#pragma unroll
            for (int nt = 0; nt < 2; nt++)
#pragma unroll
                for (int mt = 0; mt < 2; mt++)
                    mma_bf16(acc[mt][nt][0], acc[mt][nt][1], acc[mt][nt][2], acc[mt][nt][3],
                             al[mt][0], al[mt][1], al[mt][2], al[mt][3], bh0[nt], bh1[nt]);
        }
    }

    float* gM = g_Mpart[blockIdx.y];
#pragma unroll
    for (int mt = 0; mt < 2; mt++) {
#pragma unroll
        for (int nt = 0; nt < 2; nt++) {
            int c0 = mt * 16 + g;
            int d0 = dbase + w * 16 + nt * 8 + t * 2;
            if (c0 < NOUT) {
                gM[(size_t)c0 * KD + d0]     = acc[mt][nt][0];
                gM[(size_t)c0 * KD + d0 + 1] = acc[mt][nt][1];
            }
            if (c0 + 8 < NOUT) {
                gM[(size_t)(c0 + 8) * KD + d0]     = acc[mt][nt][2];
                gM[(size_t)(c0 + 8) * KD + d0 + 1] = acc[mt][nt][3];
            }
        }
    }
}

// ---------------- combine h-split partials (bounds-guarded!) ----------------
#define MADD_N (NOUT * KD / 4)    // 156800 float4
__global__ void k_madd() {
    int i = blockIdx.x * 256 + threadIdx.x;
    if (i < MADD_N) {
        const float4* a = (const float4*)g_Mpart[0];
        const float4* b = (const float4*)g_Mpart[1];
        float4 va = a[i], vb = b[i];
        ((float4*)g_M)[i] = make_float4(va.x + vb.x, va.y + vb.y, va.z + vb.z, va.w + vb.w);
    }
}

// ---------------- k2: logits partials = feats @ M^T via HMMA ----------------
__global__ __launch_bounds__(256, 2) void k2_tensor(const float* __restrict__ feats) {
    __shared__ u32 sAhi[128][17], sAlo[128][17];
    __shared__ u32 sBhi[32][17],  sBlo[32][17];
    int tid = threadIdx.x, w = tid >> 5, lane = tid & 31;
    int g = lane >> 2, t = lane & 3;
    int rowbase = blockIdx.x * 128;
    int kstart = blockIdx.y * KPER2;

    if (tid < 7 * 17) {
        sBhi[25 + tid / 17][tid % 17] = 0u;
        sBlo[25 + tid / 17][tid % 17] = 0u;
    }

    float acc[4][4];
#pragma unroll
    for (int nt = 0; nt < 4; nt++)
#pragma unroll
        for (int j = 0; j < 4; j++) acc[nt][j] = 0.f;

    float4 fa[4], fb;
    {
#pragma unroll
        for (int i = 0; i < 4; i++) {
            int u = tid + 256 * i;
            fa[i] = *(const float4*)(feats + (size_t)(rowbase + (u >> 3)) * KD + kstart + (u & 7) * 4);
        }
        if (tid < 200)
            fb = *(const float4*)(g_M + (size_t)(tid >> 3) * KD + kstart + (tid & 7) * 4);
    }

    for (int ch = 0; ch < K2CH; ch++) {
        __syncthreads();
#pragma unroll
        for (int i = 0; i < 4; i++) {
            int u = tid + 256 * i, row = u >> 3, kq = u & 7;
            u32 h0, l0, h1, l1;
            cvt_split(fa[i].x, fa[i].y, h0, l0);
            cvt_split(fa[i].z, fa[i].w, h1, l1);
            sAhi[row][kq * 2] = h0; sAhi[row][kq * 2 + 1] = h1;
            sAlo[row][kq * 2] = l0; sAlo[row][kq * 2 + 1] = l1;
        }
        if (tid < 200) {
            int c = tid >> 3, kq = tid & 7;
            u32 h0, l0, h1, l1;
            cvt_split(fb.x, fb.y, h0, l0);
            cvt_split(fb.z, fb.w, h1, l1);
            sBhi[c][kq * 2] = h0; sBhi[c][kq * 2 + 1] = h1;
            sBlo[c][kq * 2] = l0; sBlo[c][kq * 2 + 1] = l1;
        }
        __syncthreads();
        if (ch + 1 < K2CH) {
            int k0 = kstart + (ch + 1) * 32;
#pragma unroll
            for (int i = 0; i < 4; i++) {
                int u = tid + 256 * i;
                fa[i] = *(const float4*)(feats + (size_t)(rowbase + (u >> 3)) * KD + k0 + (u & 7) * 4);
            }
            if (tid < 200)
                fb = *(const float4*)(g_M + (size_t)(tid >> 3) * KD + k0 + (tid & 7) * 4);
        }
#pragma unroll
        for (int kk = 0; kk < 2; kk++) {
            int kp = kk * 8 + t;
            int r0 = w * 16 + g;
            u32 a0h = sAhi[r0][kp],     a1h = sAhi[r0 + 8][kp];
            u32 a2h = sAhi[r0][kp + 4], a3h = sAhi[r0 + 8][kp + 4];
            u32 a0l = sAlo[r0][kp],     a1l = sAlo[r0 + 8][kp];
            u32 a2l = sAlo[r0][kp + 4], a3l = sAlo[r0 + 8][kp + 4];
            u32 bh0[4], bh1[4], bl0[4], bl1[4];
#pragma unroll
            for (int nt = 0; nt < 4; nt++) {
                int n = nt * 8 + g;
                bh0[nt] = sBhi[n][kp]; bh1[nt] = sBhi[n][kp + 4];
                bl0[nt] = sBlo[n][kp]; bl1[nt] = sBlo[n][kp + 4];
            }
#pragma unroll
            for (int nt = 0; nt < 4; nt++)
                mma_bf16(acc[nt][0], acc[nt][1], acc[nt][2], acc[nt][3],
                         a0h, a1h, a2h, a3h, bh0[nt], bh1[nt]);
#pragma unroll
            for (int nt = 0; nt < 4; nt++)
                mma_bf16(acc[nt][0], acc[nt][1], acc[nt][2], acc[nt][3],
                         a0h, a1h, a2h, a3h, bl0[nt], bl1[nt]);
#pragma unroll
            for (int nt = 0; nt < 4; nt++)
                mma_bf16(acc[nt][0], acc[nt][1], acc[nt][2], acc[nt][3],
                         a0l, a1l, a2l, a3l, bh0[nt], bh1[nt]);
        }
    }

    float* gp = g_p2 + (size_t)(blockIdx.y * 16 + blockIdx.x) * 4096;
#pragma unroll
    for (int nt = 0; nt < 4; nt++) {
        int rl = w * 16 + g, c0 = nt * 8 + t * 2;
        gp[rl * 32 + c0]           = acc[nt][0];
        gp[rl * 32 + c0 + 1]       = acc[nt][1];
        gp[(rl + 8) * 32 + c0]     = acc[nt][2];
        gp[(rl + 8) * 32 + c0 + 1] = acc[nt][3];
    }
}

// ---------------- k2r: sum 28 seg partials + softmax/argmax/box decode ----------------
__global__ __launch_bounds__(256) void k2r(const float* __restrict__ props) {
    int tid = threadIdx.x, lane = tid & 31;
    int row = blockIdx.x * 8 + (tid >> 5);
    int rg = row >> 7, rl = row & 127;

    float t[NOUT];
#pragma unroll
    for (int c = 0; c < NOUT; c++) t[c] = 0.f;
    if (lane < KSPLIT2) {
        const float* base = g_p2 + (size_t)(lane * 16 + rg) * 4096 + rl * 32;
#pragma unroll
        for (int c = 0; c < NOUT; c++) t[c] = base[c];
    }
#pragma unroll
    for (int c = 0; c < NOUT; c++) {
#pragma unroll
        for (int o = 16; o > 0; o >>= 1) t[c] += __shfl_xor_sync(0xffffffffu, t[c], o);
    }

    if (lane == 0) {
#pragma unroll
        for (int c = 0; c < NOUT; c++) t[c] += g_biasf[c];
        float m = t[0]; int idx = 0;
#pragma unroll
        for (int c = 1; c < NCLS_; c++) { if (t[c] > m) { m = t[c]; idx = c; } }
        float ssum = 0.f;
#pragma unroll
        for (int c = 0; c < NCLS_; c++) ssum += expf(t[c] - m);
        float score = 1.f / ssum;
        bool valid = (idx != 0) && (score >= 0.01f);
        float p0 = props[row * 4 + 0], p1 = props[row * 4 + 1];
        float p2 = props[row * 4 + 2], p3 = props[row * 4 + 3];
        g_score[row] = valid ? score : 0.f;
        g_boxes[row * 4 + 0] = p0 + p2 * t[NCLS_ + 0];
        g_boxes[row * 4 + 1] = p1 + p3 * t[NCLS_ + 1];
        g_boxes[row * 4 + 2] = p2 * expf(t[NCLS_ + 2]);
        g_boxes[row * 4 + 3] = p3 * expf(t[NCLS_ + 3]);
    }
}

// ---------------- k3: exact greedy NMS per batch ----------------
__global__ __launch_bounds__(512) void k3_nms(float* __restrict__ out) {
    __shared__ float sraw[512];
    __shared__ float ss[512], sx0[512], sy0[512], sx1[512], sy1[512], sa[512];
    __shared__ short sord[512];
    __shared__ unsigned char ssup[512];

    int b = blockIdx.x, t = threadIdx.x;
    int gi = b * 512 + t;
    float sc = g_score[gi];
    sraw[t] = sc;
    float bx = g_boxes[gi * 4 + 0], by = g_boxes[gi * 4 + 1];
    float bw = g_boxes[gi * 4 + 2], bh = g_boxes[gi * 4 + 3];
    __syncthreads();

    int r = 0;
    for (int i = 0; i < 512; i++) {
        float si = sraw[i];
        r += (si > sc) || (si == sc && i < t);
    }

    float x0 = fminf(fmaxf(bx, 0.f), 599.f);
    float y0 = fminf(fmaxf(by, 0.f), 599.f);
    float x1 = fminf(fmaxf(bx + bw - 1.f, 0.f), 599.f);
    float y1 = fminf(fmaxf(by + bh - 1.f, 0.f), 599.f);
    float area = fmaxf(x1 - x0 + 1.f, 0.f) * fmaxf(y1 - y0 + 1.f, 0.f);

    ss[r] = sc; sx0[r] = x0; sy0[r] = y0; sx1[r] = x1; sy1[r] = y1; sa[r] = area;
    sord[r] = (short)t;
    ssup[t] = 0;
    __syncthreads();

    for (int i = 0; i < 512; i++) {
        bool alive = (!ssup[i]) && (ss[i] > 0.f);
        if (alive && t != i) {
            float ix0 = fmaxf(sx0[i], sx0[t]);
            float iy0 = fmaxf(sy0[i], sy0[t]);
            float ix1 = fminf(sx1[i], sx1[t]);
            float iy1 = fminf(sy1[i], sy1[t]);
            float inter = fmaxf(ix1 - ix0 + 1.f, 0.f) * fmaxf(iy1 - iy0 + 1.f, 0.f);
            float iou = inter / (sa[i] + sa[t] - inter + 1e-9f);
            if (iou > 0.5f) ssup[t] = 1;
        }
        __syncthreads();
    }

    bool keep = (!ssup[t]) && (ss[t] > 0.f);
    int orig = sord[t];
    int go = b * 512 + orig;

    out[go] = keep ? ss[t] : 0.f;

    float obx = g_boxes[go * 4 + 0], oby = g_boxes[go * 4 + 1];
    float obw = g_boxes[go * 4 + 2], obh = g_boxes[go * 4 + 3];
    float* ob = out + NROI + (size_t)go * 4;
    if (keep) {
        ob[0] = obx; ob[1] = oby;
        ob[2] = obx + obw - 1.f;
        ob[3] = oby + obh - 1.f;
    } else {
        ob[0] = 0.f; ob[1] = 0.f; ob[2] = -1.f; ob[3] = -1.f;
    }
}

extern "C" void kernel_launch(void* const* d_in, const int* in_sizes, int n_in,
                              void* d_out, int out_size) {
    (void)in_sizes; (void)n_in; (void)out_size;
    const float* rois  = (const float*)d_in[0];
    const float* props = (const float*)d_in[1];
    const float* W1    = (const float*)d_in[2];
    const float* b1    = (const float*)d_in[3];
    const float* Wc    = (const float*)d_in[4];
    const float* bc    = (const float*)d_in[5];
    const float* Wr    = (const float*)d_in[6];
    const float* br    = (const float*)d_in[7];
    float* out = (float*)d_out;

    k_bias<<<NOUT, 256>>>(b1, Wc, bc, Wr, br);               // launch 1
    k1_tensor<<<dim3(KD / 128, HSPL), 256>>>(W1, Wc, Wr);    // launch 2 (392 CTAs)
    k_madd<<<(MADD_N + 255) / 256, 256>>>();                 // launch 3 (613 blocks, guarded)
    k2_tensor<<<dim3(16, KSPLIT2), 256>>>(rois);             // launch 4 -> ncu
    k2r<<<NROI / 8, 256>>>(props);                           // launch 5
    k3_nms<<<4, 512>>>(out);                                 // launch 6
}

// round 13
// speedup vs baseline: 1.5322x; 1.0089x over previous
#include <cuda_runtime.h>
#include <cuda_bf16.h>
#include <cstdint>

typedef unsigned long long u64;
typedef unsigned int u32;

#define KD 25088
#define KH 4096
#define NROI 2048
#define NOUT 25
#define NCLS_ 21
#define KSPLIT2 28
#define KPER2 (KD / KSPLIT2)      // 896
#define K2CH (KPER2 / 32)         // 28
#define HSPL 2
#define KHPER (KH / HSPL)         // 2048
#define K1CH (KHPER / 32)         // 64

// ---- mma.sync m16n8k16 bf16 (validated; rel_err ~1e-5) ----
__device__ __forceinline__ void mma_bf16(float& d0, float& d1, float& d2, float& d3,
                                         u32 a0, u32 a1, u32 a2, u32 a3,
                                         u32 b0, u32 b1) {
    asm volatile(
        "mma.sync.aligned.m16n8k16.row.col.f32.bf16.bf16.f32 "
        "{%0,%1,%2,%3}, {%4,%5,%6,%7}, {%8,%9}, {%0,%1,%2,%3};"
        : "+f"(d0), "+f"(d1), "+f"(d2), "+f"(d3)
        : "r"(a0), "r"(a1), "r"(a2), "r"(a3), "r"(b0), "r"(b1));
}

__device__ __forceinline__ void ldsm_x4(u32* r, u32 addr) {
    asm volatile("ldmatrix.sync.aligned.m8n8.x4.shared.b16 {%0,%1,%2,%3}, [%4];"
        : "=r"(r[0]), "=r"(r[1]), "=r"(r[2]), "=r"(r[3]) : "r"(addr));
}

__device__ __forceinline__ u32 smem_u32(const void* p) {
    u32 a;
    asm("{ .reg .u64 t; cvta.to.shared.u64 t, %1; cvt.u32.u64 %0, t; }" : "=r"(a) : "l"(p));
    return a;
}

__device__ __forceinline__ void cvt_split(float x, float y, u32& hi, u32& lo) {
    asm("cvt.rn.bf16x2.f32 %0, %1, %2;" : "=r"(hi) : "f"(y), "f"(x));
    float rx = x - __uint_as_float(hi << 16);
    float ry = y - __uint_as_float(hi & 0xFFFF0000u);
    asm("cvt.rn.bf16x2.f32 %0, %1, %2;" : "=r"(lo) : "f"(ry), "f"(rx));
}

// scratch
__device__ __align__(16) float g_Mpart[HSPL][NOUT * KD];                // 5 MB
__device__ __align__(16) float g_p2[(size_t)KSPLIT2 * 16 * 128 * 32];   // 7 MB
__device__ float g_biasf[NOUT];
__device__ float g_score[NROI];
__device__ __align__(16) float g_boxes[NROI * 4];

__global__ void k_dummy() {}

// ---------------- fused bias ----------------
__global__ void k_bias(const float* __restrict__ b1, const float* __restrict__ Wc,
                       const float* __restrict__ bc, const float* __restrict__ Wr,
                       const float* __restrict__ br) {
    int c = blockIdx.x;
    int tid = threadIdx.x;
    const float* p = (c < NCLS_) ? (Wc + (size_t)c * KH) : (Wr + (size_t)(c - NCLS_) * KH);
    float s = 0.f;
    for (int h = tid; h < KH; h += 256) s += b1[h] * p[h];
    __shared__ float red[256];
    red[tid] = s;
    __syncthreads();
    for (int o = 128; o > 0; o >>= 1) {
        if (tid < o) red[tid] += red[tid + o];
        __syncthreads();
    }
    if (tid == 0) g_biasf[c] = red[0] + ((c < NCLS_) ? bc[c] : br[c - NCLS_]);
}

// ---------------- k1: M partial = P @ W1 (h-range) via HMMA (unchanged, validated) ----------------
__global__ __launch_bounds__(256, 2) void k1_tensor(const float* __restrict__ W1,
                                                    const float* __restrict__ Wc,
                                                    const float* __restrict__ Wr) {
    __shared__ u32 sBhi[16][132], sBlo[16][132];   // [k-pair][d]
    __shared__ u32 sAhi[32][17],  sAlo[32][17];    // [c][k-pair]
    int tid = threadIdx.x, w = tid >> 5, lane = tid & 31;
    int g = lane >> 2, t = lane & 3;
    int dbase = blockIdx.x * 128;
    int hbase = blockIdx.y * KHPER;

    if (tid < 7 * 17) {
        sAhi[25 + tid / 17][tid % 17] = 0u;
        sAlo[25 + tid / 17][tid % 17] = 0u;
    }

    float acc[2][2][4];
#pragma unroll
    for (int mt = 0; mt < 2; mt++)
#pragma unroll
        for (int nt = 0; nt < 2; nt++)
#pragma unroll
            for (int j = 0; j < 4; j++) acc[mt][nt][j] = 0.f;

    int ac = tid >> 3, akq = tid & 7;
    const float* asrc = (tid < 200)
        ? ((ac < NCLS_) ? Wc + (size_t)ac * KH : Wr + (size_t)(ac - NCLS_) * KH) : Wc;

    float4 wv0[2], wv1[2], av;
    {
#pragma unroll
        for (int i = 0; i < 2; i++) {
            int u = tid + 256 * i;
            int rp = u >> 5, f4 = u & 31;
            const float* p = W1 + (size_t)(hbase + 2 * rp) * KD + dbase + 4 * f4;
            wv0[i] = *(const float4*)p;
            wv1[i] = *(const float4*)(p + KD);
        }
        if (tid < 200) av = *(const float4*)(asrc + hbase + akq * 4);
    }

    for (int ch = 0; ch < K1CH; ch++) {
        __syncthreads();
#pragma unroll
        for (int i = 0; i < 2; i++) {
            int u = tid + 256 * i;
            int rp = u >> 5, f4 = u & 31;
            const float* x0 = (const float*)&wv0[i];
            const float* x1 = (const float*)&wv1[i];
            u32 hi[4], lo[4];
#pragma unroll
            for (int j = 0; j < 4; j++) cvt_split(x0[j], x1[j], hi[j], lo[j]);
            *(uint4*)&sBhi[rp][4 * f4] = make_uint4(hi[0], hi[1], hi[2], hi[3]);
            *(uint4*)&sBlo[rp][4 * f4] = make_uint4(lo[0], lo[1], lo[2], lo[3]);
        }
        if (tid < 200) {
            u32 h0, l0, h1, l1;
            cvt_split(av.x, av.y, h0, l0);
            cvt_split(av.z, av.w, h1, l1);
            sAhi[ac][akq * 2] = h0; sAhi[ac][akq * 2 + 1] = h1;
            sAlo[ac][akq * 2] = l0; sAlo[ac][akq * 2 + 1] = l1;
        }
        __syncthreads();
        if (ch + 1 < K1CH) {
            int h0 = hbase + (ch + 1) * 32;
#pragma unroll
            for (int i = 0; i < 2; i++) {
                int u = tid + 256 * i;
                int rp = u >> 5, f4 = u & 31;
                const float* p = W1 + (size_t)(h0 + 2 * rp) * KD + dbase + 4 * f4;
                wv0[i] = *(const float4*)p;
                wv1[i] = *(const float4*)(p + KD);
            }
            if (tid < 200) av = *(const float4*)(asrc + h0 + akq * 4);
        }
#pragma unroll
        for (int kk = 0; kk < 2; kk++) {
            int kp = kk * 8 + t;
            u32 ah[2][4], al[2][4];
#pragma unroll
            for (int mt = 0; mt < 2; mt++) {
                int r = mt * 16 + g;
                ah[mt][0] = sAhi[r][kp];     ah[mt][1] = sAhi[r + 8][kp];
                ah[mt][2] = sAhi[r][kp + 4]; ah[mt][3] = sAhi[r + 8][kp + 4];
                al[mt][0] = sAlo[r][kp];     al[mt][1] = sAlo[r + 8][kp];
                al[mt][2] = sAlo[r][kp + 4]; al[mt][3] = sAlo[r + 8][kp + 4];
            }
            u32 bh0[2], bh1[2], bl0[2], bl1[2];
#pragma unroll
            for (int nt = 0; nt < 2; nt++) {
                int d = w * 16 + nt * 8 + g;
                bh0[nt] = sBhi[kp][d]; bh1[nt] = sBhi[kp + 4][d];
                bl0[nt] = sBlo[kp][d]; bl1[nt] = sBlo[kp + 4][d];
            }
#pragma unroll
            for (int nt = 0; nt < 2; nt++)
#pragma unroll
                for (int mt = 0; mt < 2; mt++)
                    mma_bf16(acc[mt][nt][0], acc[mt][nt][1], acc[mt][nt][2], acc[mt][nt][3],
                             ah[mt][0], ah[mt][1], ah[mt][2], ah[mt][3], bh0[nt], bh1[nt]);
#pragma unroll
            for (int nt = 0; nt < 2; nt++)
#pragma unroll
                for (int mt = 0; mt < 2; mt++)
                    mma_bf16(acc[mt][nt][0], acc[mt][nt][1], acc[mt][nt][2], acc[mt][nt][3],
                             ah[mt][0], ah[mt][1], ah[mt][2], ah[mt][3], bl0[nt], bl1[nt]);
#pragma unroll
            for (int nt = 0; nt < 2; nt++)
#pragma unroll
                for (int mt = 0; mt < 2; mt++)
                    mma_bf16(acc[mt][nt][0], acc[mt][nt][1], acc[mt][nt][2], acc[mt][nt][3],
                             al[mt][0], al[mt][1], al[mt][2], al[mt][3], bh0[nt], bh1[nt]);
        }
    }

    float* gM = g_Mpart[blockIdx.y];
#pragma unroll
    for (int mt = 0; mt < 2; mt++) {
#pragma unroll
        for (int nt = 0; nt < 2; nt++) {
            int c0 = mt * 16 + g;
            int d0 = dbase + w * 16 + nt * 8 + t * 2;
            if (c0 < NOUT) {
                gM[(size_t)c0 * KD + d0]     = acc[mt][nt][0];
                gM[(size_t)c0 * KD + d0 + 1] = acc[mt][nt][1];
            }
            if (c0 + 8 < NOUT) {
                gM[(size_t)(c0 + 8) * KD + d0]     = acc[mt][nt][2];
                gM[(size_t)(c0 + 8) * KD + d0 + 1] = acc[mt][nt][3];
            }
        }
    }
}

// ---------------- k2: logits partials via HMMA + ldmatrix; fuses the h-split add ----------------
// pitch 20: 20j mod 32 = {0,20,8,28,16,4,24,12} -> conflict-free LDSM rows.
__global__ __launch_bounds__(256, 2) void k2_tensor(const float* __restrict__ feats) {
    __shared__ u32 sAhi[128][20], sAlo[128][20];
    __shared__ u32 sBhi[32][20],  sBlo[32][20];
    int tid = threadIdx.x, w = tid >> 5, lane = tid & 31;
    int g = lane >> 2, t = lane & 3;
    int rowbase = blockIdx.x * 128;
    int kstart = blockIdx.y * KPER2;

    if (tid < 7 * 20) {
        sBhi[25 + tid / 20][tid % 20] = 0u;
        sBlo[25 + tid / 20][tid % 20] = 0u;
    }

    // ldmatrix lane addresses (bytes), fixed per thread; kk adds 32 B (8 words)
    u32 aHi = smem_u32(&sAhi[w * 16 + (lane & 15)][(lane >> 4) * 4]);
    u32 aLo = smem_u32(&sAlo[w * 16 + (lane & 15)][(lane >> 4) * 4]);
    int bn = ((lane >> 4) << 3) + (lane & 7);
    int bwo = ((lane >> 3) & 1) * 4;
    u32 bHi = smem_u32(&sBhi[bn][bwo]);
    u32 bLo = smem_u32(&sBlo[bn][bwo]);
    const u32 BT = 16 * 20 * 4;   // +16 n rows

    float acc[4][4];
#pragma unroll
    for (int nt = 0; nt < 4; nt++)
#pragma unroll
        for (int j = 0; j < 4; j++) acc[nt][j] = 0.f;

    float4 fa[4], fb0, fb1;
    {
#pragma unroll
        for (int i = 0; i < 4; i++) {
            int u = tid + 256 * i;
            fa[i] = *(const float4*)(feats + (size_t)(rowbase + (u >> 3)) * KD + kstart + (u & 7) * 4);
        }
        if (tid < 200) {
            size_t off = (size_t)(tid >> 3) * KD + kstart + (tid & 7) * 4;
            fb0 = *(const float4*)(g_Mpart[0] + off);
            fb1 = *(const float4*)(g_Mpart[1] + off);
        }
    }

    for (int ch = 0; ch < K2CH; ch++) {
        __syncthreads();
#pragma unroll
        for (int i = 0; i < 4; i++) {
            int u = tid + 256 * i, row = u >> 3, kq = u & 7;
            u32 h0, l0, h1, l1;
            cvt_split(fa[i].x, fa[i].y, h0, l0);
            cvt_split(fa[i].z, fa[i].w, h1, l1);
            sAhi[row][kq * 2] = h0; sAhi[row][kq * 2 + 1] = h1;
            sAlo[row][kq * 2] = l0; sAlo[row][kq * 2 + 1] = l1;
        }
        if (tid < 200) {
            int c = tid >> 3, kq = tid & 7;
            u32 h0, l0, h1, l1;
            cvt_split(fb0.x + fb1.x, fb0.y + fb1.y, h0, l0);
            cvt_split(fb0.z + fb1.z, fb0.w + fb1.w, h1, l1);
            sBhi[c][kq * 2] = h0; sBhi[c][kq * 2 + 1] = h1;
            sBlo[c][kq * 2] = l0; sBlo[c][kq * 2 + 1] = l1;
        }
        __syncthreads();
        if (ch + 1 < K2CH) {
            int k0 = kstart + (ch + 1) * 32;
#pragma unroll
            for (int i = 0; i < 4; i++) {
                int u = tid + 256 * i;
                fa[i] = *(const float4*)(feats + (size_t)(rowbase + (u >> 3)) * KD + k0 + (u & 7) * 4);
            }
            if (tid < 200) {
                size_t off = (size_t)(tid >> 3) * KD + k0 + (tid & 7) * 4;
                fb0 = *(const float4*)(g_Mpart[0] + off);
                fb1 = *(const float4*)(g_Mpart[1] + off);
            }
        }
#pragma unroll
        for (int kk = 0; kk < 2; kk++) {
            u32 ko = kk * 32;   // 8 words = 32 bytes
            u32 ah[4], al[4], bh[8], bl[8];
            ldsm_x4(ah, aHi + ko);
            ldsm_x4(al, aLo + ko);
            ldsm_x4(bh,     bHi + ko);
            ldsm_x4(bh + 4, bHi + BT + ko);
            ldsm_x4(bl,     bLo + ko);
            ldsm_x4(bl + 4, bLo + BT + ko);
#pragma unroll
            for (int nt = 0; nt < 4; nt++)
                mma_bf16(acc[nt][0], acc[nt][1], acc[nt][2], acc[nt][3],
                         ah[0], ah[1], ah[2], ah[3], bh[2 * nt], bh[2 * nt + 1]);
#pragma unroll
            for (int nt = 0; nt < 4; nt++)
                mma_bf16(acc[nt][0], acc[nt][1], acc[nt][2], acc[nt][3],
                         ah[0], ah[1], ah[2], ah[3], bl[2 * nt], bl[2 * nt + 1]);
#pragma unroll
            for (int nt = 0; nt < 4; nt++)
                mma_bf16(acc[nt][0], acc[nt][1], acc[nt][2], acc[nt][3],
                         al[0], al[1], al[2], al[3], bh[2 * nt], bh[2 * nt + 1]);
        }
    }

    float* gp = g_p2 + (size_t)(blockIdx.y * 16 + blockIdx.x) * 4096;
#pragma unroll
    for (int nt = 0; nt < 4; nt++) {
        int rl = w * 16 + g, c0 = nt * 8 + t * 2;
        gp[rl * 32 + c0]           = acc[nt][0];
        gp[rl * 32 + c0 + 1]       = acc[nt][1];
        gp[(rl + 8) * 32 + c0]     = acc[nt][2];
        gp[(rl + 8) * 32 + c0 + 1] = acc[nt][3];
    }
}

// ---------------- k2r: sum 28 seg partials + softmax/argmax/box decode ----------------
__global__ __launch_bounds__(256) void k2r(const float* __restrict__ props) {
    int tid = threadIdx.x, lane = tid & 31;
    int row = blockIdx.x * 8 + (tid >> 5);
    int rg = row >> 7, rl = row & 127;

    float t[NOUT];
#pragma unroll
    for (int c = 0; c < NOUT; c++) t[c] = 0.f;
    if (lane < KSPLIT2) {
        const float* base = g_p2 + (size_t)(lane * 16 + rg) * 4096 + rl * 32;
#pragma unroll
        for (int c = 0; c < NOUT; c++) t[c] = base[c];
    }
#pragma unroll
    for (int c = 0; c < NOUT; c++) {
#pragma unroll
        for (int o = 16; o > 0; o >>= 1) t[c] += __shfl_xor_sync(0xffffffffu, t[c], o);
    }

    if (lane == 0) {
#pragma unroll
        for (int c = 0; c < NOUT; c++) t[c] += g_biasf[c];
        float m = t[0]; int idx = 0;
#pragma unroll
        for (int c = 1; c < NCLS_; c++) { if (t[c] > m) { m = t[c]; idx = c; } }
        float ssum = 0.f;
#pragma unroll
        for (int c = 0; c < NCLS_; c++) ssum += expf(t[c] - m);
        float score = 1.f / ssum;
        bool valid = (idx != 0) && (score >= 0.01f);
        float p0 = props[row * 4 + 0], p1 = props[row * 4 + 1];
        float p2 = props[row * 4 + 2], p3 = props[row * 4 + 3];
        g_score[row] = valid ? score : 0.f;
        g_boxes[row * 4 + 0] = p0 + p2 * t[NCLS_ + 0];
        g_boxes[row * 4 + 1] = p1 + p3 * t[NCLS_ + 1];
        g_boxes[row * 4 + 2] = p2 * expf(t[NCLS_ + 2]);
        g_boxes[row * 4 + 3] = p3 * expf(t[NCLS_ + 3]);
    }
}

// ---------------- k3: exact greedy NMS per batch ----------------
__global__ __launch_bounds__(512) void k3_nms(float* __restrict__ out) {
    __shared__ float sraw[512];
    __shared__ float ss[512], sx0[512], sy0[512], sx1[512], sy1[512], sa[512];
    __shared__ short sord[512];
    __shared__ unsigned char ssup[512];

    int b = blockIdx.x, t = threadIdx.x;
    int gi = b * 512 + t;
    float sc = g_score[gi];
    sraw[t] = sc;
    float bx = g_boxes[gi * 4 + 0], by = g_boxes[gi * 4 + 1];
    float bw = g_boxes[gi * 4 + 2], bh = g_boxes[gi * 4 + 3];
    __syncthreads();

    int r = 0;
    for (int i = 0; i < 512; i++) {
        float si = sraw[i];
        r += (si > sc) || (si == sc && i < t);
    }

    float x0 = fminf(fmaxf(bx, 0.f), 599.f);
    float y0 = fminf(fmaxf(by, 0.f), 599.f);
    float x1 = fminf(fmaxf(bx + bw - 1.f, 0.f), 599.f);
    float y1 = fminf(fmaxf(by + bh - 1.f, 0.f), 599.f);
    float area = fmaxf(x1 - x0 + 1.f, 0.f) * fmaxf(y1 - y0 + 1.f, 0.f);

    ss[r] = sc; sx0[r] = x0; sy0[r] = y0; sx1[r] = x1; sy1[r] = y1; sa[r] = area;
    sord[r] = (short)t;
    ssup[t] = 0;
    __syncthreads();

    for (int i = 0; i < 512; i++) {
        bool alive = (!ssup[i]) && (ss[i] > 0.f);
        if (alive && t != i) {
            float ix0 = fmaxf(sx0[i], sx0[t]);
            float iy0 = fmaxf(sy0[i], sy0[t]);
            float ix1 = fminf(sx1[i], sx1[t]);
            float iy1 = fminf(sy1[i], sy1[t]);
            float inter = fmaxf(ix1 - ix0 + 1.f, 0.f) * fmaxf(iy1 - iy0 + 1.f, 0.f);
            float iou = inter / (sa[i] + sa[t] - inter + 1e-9f);
            if (iou > 0.5f) ssup[t] = 1;
        }
        __syncthreads();
    }

    bool keep = (!ssup[t]) && (ss[t] > 0.f);
    int orig = sord[t];
    int go = b * 512 + orig;

    out[go] = keep ? ss[t] : 0.f;

    float obx = g_boxes[go * 4 + 0], oby = g_boxes[go * 4 + 1];
    float obw = g_boxes[go * 4 + 2], obh = g_boxes[go * 4 + 3];
    float* ob = out + NROI + (size_t)go * 4;
    if (keep) {
        ob[0] = obx; ob[1] = oby;
        ob[2] = obx + obw - 1.f;
        ob[3] = oby + obh - 1.f;
    } else {
        ob[0] = 0.f; ob[1] = 0.f; ob[2] = -1.f; ob[3] = -1.f;
    }
}

extern "C" void kernel_launch(void* const* d_in, const int* in_sizes, int n_in,
                              void* d_out, int out_size) {
    (void)in_sizes; (void)n_in; (void)out_size;
    const float* rois  = (const float*)d_in[0];
    const float* props = (const float*)d_in[1];
    const float* W1    = (const float*)d_in[2];
    const float* b1    = (const float*)d_in[3];
    const float* Wc    = (const float*)d_in[4];
    const float* bc    = (const float*)d_in[5];
    const float* Wr    = (const float*)d_in[6];
    const float* br    = (const float*)d_in[7];
    float* out = (float*)d_out;

    k_bias<<<NOUT, 256>>>(b1, Wc, bc, Wr, br);               // launch 1
    k_dummy<<<1, 32>>>();                                    // launch 2
    k_dummy<<<1, 32>>>();                                    // launch 3
    k1_tensor<<<dim3(KD / 128, HSPL), 256>>>(W1, Wc, Wr);    // launch 4 -> ncu captures k1
    k2_tensor<<<dim3(16, KSPLIT2), 256>>>(rois);             // launch 5
    k2r<<<NROI / 8, 256>>>(props);                           // launch 6
    k3_nms<<<4, 512>>>(out);                                 // launch 7
}

// round 14
// speedup vs baseline: 1.5918x; 1.0389x over previous
#include <cuda_runtime.h>
#include <cuda_bf16.h>
#include <cstdint>

typedef unsigned long long u64;
typedef unsigned int u32;

#define KD 25088
#define KH 4096
#define NROI 2048
#define NOUT 25
#define NCLS_ 21
#define KSPLIT2 28
#define KPER2 (KD / KSPLIT2)      // 896
#define K2CH (KPER2 / 32)         // 28
#define HSPL 2
#define KHPER (KH / HSPL)         // 2048
#define K1CH (KHPER / 32)         // 64

// ---- mma.sync m16n8k16 bf16 (validated; rel_err ~1e-5) ----
__device__ __forceinline__ void mma_bf16(float& d0, float& d1, float& d2, float& d3,
                                         u32 a0, u32 a1, u32 a2, u32 a3,
                                         u32 b0, u32 b1) {
    asm volatile(
        "mma.sync.aligned.m16n8k16.row.col.f32.bf16.bf16.f32 "
        "{%0,%1,%2,%3}, {%4,%5,%6,%7}, {%8,%9}, {%0,%1,%2,%3};"
        : "+f"(d0), "+f"(d1), "+f"(d2), "+f"(d3)
        : "r"(a0), "r"(a1), "r"(a2), "r"(a3), "r"(b0), "r"(b1));
}

__device__ __forceinline__ void ldsm_x4(u32* r, u32 addr) {
    asm volatile("ldmatrix.sync.aligned.m8n8.x4.shared.b16 {%0,%1,%2,%3}, [%4];"
        : "=r"(r[0]), "=r"(r[1]), "=r"(r[2]), "=r"(r[3]) : "r"(addr));
}
__device__ __forceinline__ void ldsm_x4_t(u32* r, u32 addr) {
    asm volatile("ldmatrix.sync.aligned.m8n8.x4.trans.shared.b16 {%0,%1,%2,%3}, [%4];"
        : "=r"(r[0]), "=r"(r[1]), "=r"(r[2]), "=r"(r[3]) : "r"(addr));
}

__device__ __forceinline__ u32 smem_u32(const void* p) {
    u32 a;
    asm("{ .reg .u64 t; cvta.to.shared.u64 t, %1; cvt.u32.u64 %0, t; }" : "=r"(a) : "l"(p));
    return a;
}

__device__ __forceinline__ void cvt_split(float x, float y, u32& hi, u32& lo) {
    asm("cvt.rn.bf16x2.f32 %0, %1, %2;" : "=r"(hi) : "f"(y), "f"(x));
    float rx = x - __uint_as_float(hi << 16);
    float ry = y - __uint_as_float(hi & 0xFFFF0000u);
    asm("cvt.rn.bf16x2.f32 %0, %1, %2;" : "=r"(lo) : "f"(ry), "f"(rx));
}

// scratch
__device__ __align__(16) float g_Mpart[HSPL][NOUT * KD];                // 5 MB
__device__ __align__(16) float g_p2[(size_t)KSPLIT2 * 16 * 128 * 32];   // 7 MB
__device__ float g_biasf[NOUT];
__device__ float g_score[NROI];
__device__ __align__(16) float g_boxes[NROI * 4];

__global__ void k_dummy() {}

// ---------------- fused bias ----------------
__global__ void k_bias(const float* __restrict__ b1, const float* __restrict__ Wc,
                       const float* __restrict__ bc, const float* __restrict__ Wr,
                       const float* __restrict__ br) {
    int c = blockIdx.x;
    int tid = threadIdx.x;
    const float* p = (c < NCLS_) ? (Wc + (size_t)c * KH) : (Wr + (size_t)(c - NCLS_) * KH);
    float s = 0.f;
    for (int h = tid; h < KH; h += 256) s += b1[h] * p[h];
    __shared__ float red[256];
    red[tid] = s;
    __syncthreads();
    for (int o = 128; o > 0; o >>= 1) {
        if (tid < o) red[tid] += red[tid + o];
        __syncthreads();
    }
    if (tid == 0) g_biasf[c] = red[0] + ((c < NCLS_) ? bc[c] : br[c - NCLS_]);
}

// ---------------- k1: M partial = P @ W1 via HMMA + ldmatrix ----------------
// B tile repacked d-adjacent: sB[h 32][dp 64, pitch 68] u32 (= [k][n] row-major b16)
// -> ldmatrix.x4.trans gives B col-major fragments. A tile [c 32][kp 16, pitch 20].
#define BP 68
__global__ __launch_bounds__(256, 2) void k1_tensor(const float* __restrict__ W1,
                                                    const float* __restrict__ Wc,
                                                    const float* __restrict__ Wr) {
    __shared__ u32 sBhi[32][BP], sBlo[32][BP];
    __shared__ u32 sAhi[32][20], sAlo[32][20];
    int tid = threadIdx.x, w = tid >> 5, lane = tid & 31;
    int g = lane >> 2, t = lane & 3;
    int dbase = blockIdx.x * 128;
    int hbase = blockIdx.y * KHPER;

    if (tid < 7 * 20) {       // zero-pad A rows 25..31
        sAhi[25 + tid / 20][tid % 20] = 0u;
        sAlo[25 + tid / 20][tid % 20] = 0u;
    }

    float acc[2][2][4];
#pragma unroll
    for (int mt = 0; mt < 2; mt++)
#pragma unroll
        for (int nt = 0; nt < 2; nt++)
#pragma unroll
            for (int j = 0; j < 4; j++) acc[mt][nt][j] = 0.f;

    int ac = tid >> 3, akq = tid & 7;
    const float* asrc = (tid < 200)
        ? ((ac < NCLS_) ? Wc + (size_t)ac * KH : Wr + (size_t)(ac - NCLS_) * KH) : Wc;

    // ldmatrix lane addresses
    u32 aHi = smem_u32(&sAhi[lane & 15][(lane >> 4) * 4]);
    u32 aLo = smem_u32(&sAlo[lane & 15][(lane >> 4) * 4]);
    const u32 AT = 16 * 20 * 4;              // +16 m rows
    u32 bHi = smem_u32(&sBhi[lane & 15][w * 8 + (lane >> 4) * 4]);
    u32 bLo = smem_u32(&sBlo[lane & 15][w * 8 + (lane >> 4) * 4]);
    const u32 BKO = 16 * BP * 4;             // +16 k rows

    float4 wv0[2], wv1[2], av;
    {
#pragma unroll
        for (int i = 0; i < 2; i++) {
            int u = tid + 256 * i;
            int rp = u >> 5, f4 = u & 31;
            const float* p = W1 + (size_t)(hbase + 2 * rp) * KD + dbase + 4 * f4;
            wv0[i] = *(const float4*)p;
            wv1[i] = *(const float4*)(p + KD);
        }
        if (tid < 200) av = *(const float4*)(asrc + hbase + akq * 4);
    }

    for (int ch = 0; ch < K1CH; ch++) {
        __syncthreads();
        // convert + store B (d-adjacent repack, STS.64 conflict-free) and A
#pragma unroll
        for (int i = 0; i < 2; i++) {
            int u = tid + 256 * i;
            int rp = u >> 5, f4 = u & 31;
            u32 h0, l0, h1, l1;
            cvt_split(wv0[i].x, wv0[i].y, h0, l0);   // (d, d+1) @ row 2rp
            cvt_split(wv0[i].z, wv0[i].w, h1, l1);   // (d+2, d+3)
            *(uint2*)&sBhi[2 * rp][2 * f4] = make_uint2(h0, h1);
            *(uint2*)&sBlo[2 * rp][2 * f4] = make_uint2(l0, l1);
            cvt_split(wv1[i].x, wv1[i].y, h0, l0);   // row 2rp+1
            cvt_split(wv1[i].z, wv1[i].w, h1, l1);
            *(uint2*)&sBhi[2 * rp + 1][2 * f4] = make_uint2(h0, h1);
            *(uint2*)&sBlo[2 * rp + 1][2 * f4] = make_uint2(l0, l1);
        }
        if (tid < 200) {
            u32 h0, l0, h1, l1;
            cvt_split(av.x, av.y, h0, l0);
            cvt_split(av.z, av.w, h1, l1);
            *(uint2*)&sAhi[ac][akq * 2] = make_uint2(h0, h1);
            *(uint2*)&sAlo[ac][akq * 2] = make_uint2(l0, l1);
        }
        __syncthreads();
        if (ch + 1 < K1CH) {
            int h0 = hbase + (ch + 1) * 32;
#pragma unroll
            for (int i = 0; i < 2; i++) {
                int u = tid + 256 * i;
                int rp = u >> 5, f4 = u & 31;
                const float* p = W1 + (size_t)(h0 + 2 * rp) * KD + dbase + 4 * f4;
                wv0[i] = *(const float4*)p;
                wv1[i] = *(const float4*)(p + KD);
            }
            if (tid < 200) av = *(const float4*)(asrc + h0 + akq * 4);
        }
#pragma unroll
        for (int kk = 0; kk < 2; kk++) {
            u32 ko = kk * 32;          // A: +8 u32 (16 k)
            u32 kob = kk * BKO;        // B: +16 k rows
            u32 ah[8], al[8], bh[4], bl[4];
            ldsm_x4(ah,     aHi + ko);
            ldsm_x4(ah + 4, aHi + AT + ko);
            ldsm_x4(al,     aLo + ko);
            ldsm_x4(al + 4, aLo + AT + ko);
            ldsm_x4_t(bh, bHi + kob);
            ldsm_x4_t(bl, bLo + kob);
#pragma unroll
            for (int mt = 0; mt < 2; mt++)
#pragma unroll
                for (int nt = 0; nt < 2; nt++)
                    mma_bf16(acc[mt][nt][0], acc[mt][nt][1], acc[mt][nt][2], acc[mt][nt][3],
                             ah[4 * mt], ah[4 * mt + 1], ah[4 * mt + 2], ah[4 * mt + 3],
                             bh[2 * nt], bh[2 * nt + 1]);
#pragma unroll
            for (int mt = 0; mt < 2; mt++)
#pragma unroll
                for (int nt = 0; nt < 2; nt++)
                    mma_bf16(acc[mt][nt][0], acc[mt][nt][1], acc[mt][nt][2], acc[mt][nt][3],
                             ah[4 * mt], ah[4 * mt + 1], ah[4 * mt + 2], ah[4 * mt + 3],
                             bl[2 * nt], bl[2 * nt + 1]);
#pragma unroll
            for (int mt = 0; mt < 2; mt++)
#pragma unroll
                for (int nt = 0; nt < 2; nt++)
                    mma_bf16(acc[mt][nt][0], acc[mt][nt][1], acc[mt][nt][2], acc[mt][nt][3],
                             al[4 * mt], al[4 * mt + 1], al[4 * mt + 2], al[4 * mt + 3],
                             bh[2 * nt], bh[2 * nt + 1]);
        }
    }

    float* gM = g_Mpart[blockIdx.y];
#pragma unroll
    for (int mt = 0; mt < 2; mt++) {
#pragma unroll
        for (int nt = 0; nt < 2; nt++) {
            int c0 = mt * 16 + g;
            int d0 = dbase + w * 16 + nt * 8 + t * 2;
            if (c0 < NOUT) {
                gM[(size_t)c0 * KD + d0]     = acc[mt][nt][0];
                gM[(size_t)c0 * KD + d0 + 1] = acc[mt][nt][1];
            }
            if (c0 + 8 < NOUT) {
                gM[(size_t)(c0 + 8) * KD + d0]     = acc[mt][nt][2];
                gM[(size_t)(c0 + 8) * KD + d0 + 1] = acc[mt][nt][3];
            }
        }
    }
}

// ---------------- k2: logits partials via HMMA + ldmatrix (validated R13) ----------------
__global__ __launch_bounds__(256, 2) void k2_tensor(const float* __restrict__ feats) {
    __shared__ u32 sAhi[128][20], sAlo[128][20];
    __shared__ u32 sBhi[32][20],  sBlo[32][20];
    int tid = threadIdx.x, w = tid >> 5, lane = tid & 31;
    int g = lane >> 2, t = lane & 3;
    int rowbase = blockIdx.x * 128;
    int kstart = blockIdx.y * KPER2;

    if (tid < 7 * 20) {
        sBhi[25 + tid / 20][tid % 20] = 0u;
        sBlo[25 + tid / 20][tid % 20] = 0u;
    }

    u32 aHi = smem_u32(&sAhi[w * 16 + (lane & 15)][(lane >> 4) * 4]);
    u32 aLo = smem_u32(&sAlo[w * 16 + (lane & 15)][(lane >> 4) * 4]);
    int bn = ((lane >> 4) << 3) + (lane & 7);
    int bwo = ((lane >> 3) & 1) * 4;
    u32 bHi = smem_u32(&sBhi[bn][bwo]);
    u32 bLo = smem_u32(&sBlo[bn][bwo]);
    const u32 BT = 16 * 20 * 4;

    float acc[4][4];
#pragma unroll
    for (int nt = 0; nt < 4; nt++)
#pragma unroll
        for (int j = 0; j < 4; j++) acc[nt][j] = 0.f;

    float4 fa[4], fb0, fb1;
    {
#pragma unroll
        for (int i = 0; i < 4; i++) {
            int u = tid + 256 * i;
            fa[i] = *(const float4*)(feats + (size_t)(rowbase + (u >> 3)) * KD + kstart + (u & 7) * 4);
        }
        if (tid < 200) {
            size_t off = (size_t)(tid >> 3) * KD + kstart + (tid & 7) * 4;
            fb0 = *(const float4*)(g_Mpart[0] + off);
            fb1 = *(const float4*)(g_Mpart[1] + off);
        }
    }

    for (int ch = 0; ch < K2CH; ch++) {
        __syncthreads();
#pragma unroll
        for (int i = 0; i < 4; i++) {
            int u = tid + 256 * i, row = u >> 3, kq = u & 7;
            u32 h0, l0, h1, l1;
            cvt_split(fa[i].x, fa[i].y, h0, l0);
            cvt_split(fa[i].z, fa[i].w, h1, l1);
            sAhi[row][kq * 2] = h0; sAhi[row][kq * 2 + 1] = h1;
            sAlo[row][kq * 2] = l0; sAlo[row][kq * 2 + 1] = l1;
        }
        if (tid < 200) {
            int c = tid >> 3, kq = tid & 7;
            u32 h0, l0, h1, l1;
            cvt_split(fb0.x + fb1.x, fb0.y + fb1.y, h0, l0);
            cvt_split(fb0.z + fb1.z, fb0.w + fb1.w, h1, l1);
            sBhi[c][kq * 2] = h0; sBhi[c][kq * 2 + 1] = h1;
            sBlo[c][kq * 2] = l0; sBlo[c][kq * 2 + 1] = l1;
        }
        __syncthreads();
        if (ch + 1 < K2CH) {
            int k0 = kstart + (ch + 1) * 32;
#pragma unroll
            for (int i = 0; i < 4; i++) {
                int u = tid + 256 * i;
                fa[i] = *(const float4*)(feats + (size_t)(rowbase + (u >> 3)) * KD + k0 + (u & 7) * 4);
            }
            if (tid < 200) {
                size_t off = (size_t)(tid >> 3) * KD + k0 + (tid & 7) * 4;
                fb0 = *(const float4*)(g_Mpart[0] + off);
                fb1 = *(const float4*)(g_Mpart[1] + off);
            }
        }
#pragma unroll
        for (int kk = 0; kk < 2; kk++) {
            u32 ko = kk * 32;
            u32 ah[4], al[4], bh[8], bl[8];
            ldsm_x4(ah, aHi + ko);
            ldsm_x4(al, aLo + ko);
            ldsm_x4(bh,     bHi + ko);
            ldsm_x4(bh + 4, bHi + BT + ko);
            ldsm_x4(bl,     bLo + ko);
            ldsm_x4(bl + 4, bLo + BT + ko);
#pragma unroll
            for (int nt = 0; nt < 4; nt++)
                mma_bf16(acc[nt][0], acc[nt][1], acc[nt][2], acc[nt][3],
                         ah[0], ah[1], ah[2], ah[3], bh[2 * nt], bh[2 * nt + 1]);
#pragma unroll
            for (int nt = 0; nt < 4; nt++)
                mma_bf16(acc[nt][0], acc[nt][1], acc[nt][2], acc[nt][3],
                         ah[0], ah[1], ah[2], ah[3], bl[2 * nt], bl[2 * nt + 1]);
#pragma unroll
            for (int nt = 0; nt < 4; nt++)
                mma_bf16(acc[nt][0], acc[nt][1], acc[nt][2], acc[nt][3],
                         al[0], al[1], al[2], al[3], bh[2 * nt], bh[2 * nt + 1]);
        }
    }

    float* gp = g_p2 + (size_t)(blockIdx.y * 16 + blockIdx.x) * 4096;
#pragma unroll
    for (int nt = 0; nt < 4; nt++) {
        int rl = w * 16 + g, c0 = nt * 8 + t * 2;
        gp[rl * 32 + c0]           = acc[nt][0];
        gp[rl * 32 + c0 + 1]       = acc[nt][1];
        gp[(rl + 8) * 32 + c0]     = acc[nt][2];
        gp[(rl + 8) * 32 + c0 + 1] = acc[nt][3];
    }
}

// ---------------- k2r: sum 28 seg partials + softmax/argmax/box decode ----------------
__global__ __launch_bounds__(256) void k2r(const float* __restrict__ props) {
    int tid = threadIdx.x, lane = tid & 31;
    int row = blockIdx.x * 8 + (tid >> 5);
    int rg = row >> 7, rl = row & 127;

    float t[NOUT];
#pragma unroll
    for (int c = 0; c < NOUT; c++) t[c] = 0.f;
    if (lane < KSPLIT2) {
        const float* base = g_p2 + (size_t)(lane * 16 + rg) * 4096 + rl * 32;
#pragma unroll
        for (int c = 0; c < NOUT; c++) t[c] = base[c];
    }
#pragma unroll
    for (int c = 0; c < NOUT; c++) {
#pragma unroll
        for (int o = 16; o > 0; o >>= 1) t[c] += __shfl_xor_sync(0xffffffffu, t[c], o);
    }

    if (lane == 0) {
#pragma unroll
        for (int c = 0; c < NOUT; c++) t[c] += g_biasf[c];
        float m = t[0]; int idx = 0;
#pragma unroll
        for (int c = 1; c < NCLS_; c++) { if (t[c] > m) { m = t[c]; idx = c; } }
        float ssum = 0.f;
#pragma unroll
        for (int c = 0; c < NCLS_; c++) ssum += expf(t[c] - m);
        float score = 1.f / ssum;
        bool valid = (idx != 0) && (score >= 0.01f);
        float p0 = props[row * 4 + 0], p1 = props[row * 4 + 1];
        float p2 = props[row * 4 + 2], p3 = props[row * 4 + 3];
        g_score[row] = valid ? score : 0.f;
        g_boxes[row * 4 + 0] = p0 + p2 * t[NCLS_ + 0];
        g_boxes[row * 4 + 1] = p1 + p3 * t[NCLS_ + 1];
        g_boxes[row * 4 + 2] = p2 * expf(t[NCLS_ + 2]);
        g_boxes[row * 4 + 3] = p3 * expf(t[NCLS_ + 3]);
    }
}

// ---------------- k3: exact greedy NMS per batch ----------------
__global__ __launch_bounds__(512) void k3_nms(float* __restrict__ out) {
    __shared__ float sraw[512];
    __shared__ float ss[512], sx0[512], sy0[512], sx1[512], sy1[512], sa[512];
    __shared__ short sord[512];
    __shared__ unsigned char ssup[512];

    int b = blockIdx.x, t = threadIdx.x;
    int gi = b * 512 + t;
    float sc = g_score[gi];
    sraw[t] = sc;
    float bx = g_boxes[gi * 4 + 0], by = g_boxes[gi * 4 + 1];
    float bw = g_boxes[gi * 4 + 2], bh = g_boxes[gi * 4 + 3];
    __syncthreads();

    int r = 0;
    for (int i = 0; i < 512; i++) {
        float si = sraw[i];
        r += (si > sc) || (si == sc && i < t);
    }

    float x0 = fminf(fmaxf(bx, 0.f), 599.f);
    float y0 = fminf(fmaxf(by, 0.f), 599.f);
    float x1 = fminf(fmaxf(bx + bw - 1.f, 0.f), 599.f);
    float y1 = fminf(fmaxf(by + bh - 1.f, 0.f), 599.f);
    float area = fmaxf(x1 - x0 + 1.f, 0.f) * fmaxf(y1 - y0 + 1.f, 0.f);

    ss[r] = sc; sx0[r] = x0; sy0[r] = y0; sx1[r] = x1; sy1[r] = y1; sa[r] = area;
    sord[r] = (short)t;
    ssup[t] = 0;
    __syncthreads();

    for (int i = 0; i < 512; i++) {
        bool alive = (!ssup[i]) && (ss[i] > 0.f);
        if (alive && t != i) {
            float ix0 = fmaxf(sx0[i], sx0[t]);
            float iy0 = fmaxf(sy0[i], sy0[t]);
            float ix1 = fminf(sx1[i], sx1[t]);
            float iy1 = fminf(sy1[i], sy1[t]);
            float inter = fmaxf(ix1 - ix0 + 1.f, 0.f) * fmaxf(iy1 - iy0 + 1.f, 0.f);
            float iou = inter / (sa[i] + sa[t] - inter + 1e-9f);
            if (iou > 0.5f) ssup[t] = 1;
        }
        __syncthreads();
    }

    bool keep = (!ssup[t]) && (ss[t] > 0.f);
    int orig = sord[t];
    int go = b * 512 + orig;

    out[go] = keep ? ss[t] : 0.f;

    float obx = g_boxes[go * 4 + 0], oby = g_boxes[go * 4 + 1];
    float obw = g_boxes[go * 4 + 2], obh = g_boxes[go * 4 + 3];
    float* ob = out + NROI + (size_t)go * 4;
    if (keep) {
        ob[0] = obx; ob[1] = oby;
        ob[2] = obx + obw - 1.f;
        ob[3] = oby + obh - 1.f;
    } else {
        ob[0] = 0.f; ob[1] = 0.f; ob[2] = -1.f; ob[3] = -1.f;
    }
}

extern "C" void kernel_launch(void* const* d_in, const int* in_sizes, int n_in,
                              void* d_out, int out_size) {
    (void)in_sizes; (void)n_in; (void)out_size;
    const float* rois  = (const float*)d_in[0];
    const float* props = (const float*)d_in[1];
    const float* W1    = (const float*)d_in[2];
    const float* b1    = (const float*)d_in[3];
    const float* Wc    = (const float*)d_in[4];
    const float* bc    = (const float*)d_in[5];
    const float* Wr    = (const float*)d_in[6];
    const float* br    = (const float*)d_in[7];
    float* out = (float*)d_out;

    k_bias<<<NOUT, 256>>>(b1, Wc, bc, Wr, br);               // launch 1
    k_dummy<<<1, 32>>>();                                    // launch 2
    k_dummy<<<1, 32>>>();                                    // launch 3
    k1_tensor<<<dim3(KD / 128, HSPL), 256>>>(W1, Wc, Wr);    // launch 4 -> ncu captures k1
    k2_tensor<<<dim3(16, KSPLIT2), 256>>>(rois);             // launch 5
    k2r<<<NROI / 8, 256>>>(props);                           // launch 6
    k3_nms<<<4, 512>>>(out);                                 // launch 7
}

// round 15
// speedup vs baseline: 2.0766x; 1.3046x over previous
#include <cuda_runtime.h>
#include <cuda_bf16.h>
#include <cstdint>

typedef unsigned long long u64;
typedef unsigned int u32;

#define KD 25088
#define KH 4096
#define NROI 2048
#define NOUT 25
#define NCLS_ 21
#define KSPLIT2 28
#define KPER2 (KD / KSPLIT2)      // 896
#define K2CH (KPER2 / 32)         // 28
#define HSPL 2
#define KHPER (KH / HSPL)         // 2048
#define K1CH (KHPER / 32)         // 64

// ---- mma.sync m16n8k16 bf16 (validated; rel_err ~1e-5) ----
__device__ __forceinline__ void mma_bf16(float& d0, float& d1, float& d2, float& d3,
                                         u32 a0, u32 a1, u32 a2, u32 a3,
                                         u32 b0, u32 b1) {
    asm volatile(
        "mma.sync.aligned.m16n8k16.row.col.f32.bf16.bf16.f32 "
        "{%0,%1,%2,%3}, {%4,%5,%6,%7}, {%8,%9}, {%0,%1,%2,%3};"
        : "+f"(d0), "+f"(d1), "+f"(d2), "+f"(d3)
        : "r"(a0), "r"(a1), "r"(a2), "r"(a3), "r"(b0), "r"(b1));
}

__device__ __forceinline__ void ldsm_x4(u32* r, u32 addr) {
    asm volatile("ldmatrix.sync.aligned.m8n8.x4.shared.b16 {%0,%1,%2,%3}, [%4];"
        : "=r"(r[0]), "=r"(r[1]), "=r"(r[2]), "=r"(r[3]) : "r"(addr));
}
__device__ __forceinline__ void ldsm_x4_t(u32* r, u32 addr) {
    asm volatile("ldmatrix.sync.aligned.m8n8.x4.trans.shared.b16 {%0,%1,%2,%3}, [%4];"
        : "=r"(r[0]), "=r"(r[1]), "=r"(r[2]), "=r"(r[3]) : "r"(addr));
}

__device__ __forceinline__ u32 smem_u32(const void* p) {
    u32 a;
    asm("{ .reg .u64 t; cvta.to.shared.u64 t, %1; cvt.u32.u64 %0, t; }" : "=r"(a) : "l"(p));
    return a;
}

__device__ __forceinline__ void cvt_split(float x, float y, u32& hi, u32& lo) {
    asm("cvt.rn.bf16x2.f32 %0, %1, %2;" : "=r"(hi) : "f"(y), "f"(x));
    float rx = x - __uint_as_float(hi << 16);
    float ry = y - __uint_as_float(hi & 0xFFFF0000u);
    asm("cvt.rn.bf16x2.f32 %0, %1, %2;" : "=r"(lo) : "f"(ry), "f"(rx));
}

// scratch
__device__ __align__(16) float g_Mpart[HSPL][NOUT * KD];                // 5 MB
__device__ __align__(16) float g_p2[(size_t)KSPLIT2 * 16 * 128 * 32];   // 7 MB
__device__ float g_biasf[NOUT];
__device__ float g_score[NROI];
__device__ __align__(16) float g_boxes[NROI * 4];
// NMS scratch
__device__ float g_ns[4][512];
__device__ float g_nx0[4][512], g_ny0[4][512], g_nx1[4][512], g_ny1[4][512], g_na[4][512];
__device__ short g_nord[4][512];
__device__ __align__(16) u32 g_mask[4][512][16];   // 128 KB bitmask

__global__ void k_dummy() {}

// ---------------- fused bias ----------------
__global__ void k_bias(const float* __restrict__ b1, const float* __restrict__ Wc,
                       const float* __restrict__ bc, const float* __restrict__ Wr,
                       const float* __restrict__ br) {
    int c = blockIdx.x;
    int tid = threadIdx.x;
    const float* p = (c < NCLS_) ? (Wc + (size_t)c * KH) : (Wr + (size_t)(c - NCLS_) * KH);
    float s = 0.f;
    for (int h = tid; h < KH; h += 256) s += b1[h] * p[h];
    __shared__ float red[256];
    red[tid] = s;
    __syncthreads();
    for (int o = 128; o > 0; o >>= 1) {
        if (tid < o) red[tid] += red[tid + o];
        __syncthreads();
    }
    if (tid == 0) g_biasf[c] = red[0] + ((c < NCLS_) ? bc[c] : br[c - NCLS_]);
}

// ---------------- k1: M partial = P @ W1 via HMMA + ldmatrix (validated R14) ----------------
#define BP 68
__global__ __launch_bounds__(256, 2) void k1_tensor(const float* __restrict__ W1,
                                                    const float* __restrict__ Wc,
                                                    const float* __restrict__ Wr) {
    __shared__ u32 sBhi[32][BP], sBlo[32][BP];
    __shared__ u32 sAhi[32][20], sAlo[32][20];
    int tid = threadIdx.x, w = tid >> 5, lane = tid & 31;
    int g = lane >> 2, t = lane & 3;
    int dbase = blockIdx.x * 128;
    int hbase = blockIdx.y * KHPER;

    if (tid < 7 * 20) {
        sAhi[25 + tid / 20][tid % 20] = 0u;
        sAlo[25 + tid / 20][tid % 20] = 0u;
    }

    float acc[2][2][4];
#pragma unroll
    for (int mt = 0; mt < 2; mt++)
#pragma unroll
        for (int nt = 0; nt < 2; nt++)
#pragma unroll
            for (int j = 0; j < 4; j++) acc[mt][nt][j] = 0.f;

    int ac = tid >> 3, akq = tid & 7;
    const float* asrc = (tid < 200)
        ? ((ac < NCLS_) ? Wc + (size_t)ac * KH : Wr + (size_t)(ac - NCLS_) * KH) : Wc;

    u32 aHi = smem_u32(&sAhi[lane & 15][(lane >> 4) * 4]);
    u32 aLo = smem_u32(&sAlo[lane & 15][(lane >> 4) * 4]);
    const u32 AT = 16 * 20 * 4;
    u32 bHi = smem_u32(&sBhi[lane & 15][w * 8 + (lane >> 4) * 4]);
    u32 bLo = smem_u32(&sBlo[lane & 15][w * 8 + (lane >> 4) * 4]);
    const u32 BKO = 16 * BP * 4;

    float4 wv0[2], wv1[2], av;
    {
#pragma unroll
        for (int i = 0; i < 2; i++) {
            int u = tid + 256 * i;
            int rp = u >> 5, f4 = u & 31;
            const float* p = W1 + (size_t)(hbase + 2 * rp) * KD + dbase + 4 * f4;
            wv0[i] = *(const float4*)p;
            wv1[i] = *(const float4*)(p + KD);
        }
        if (tid < 200) av = *(const float4*)(asrc + hbase + akq * 4);
    }

    for (int ch = 0; ch < K1CH; ch++) {
        __syncthreads();
#pragma unroll
        for (int i = 0; i < 2; i++) {
            int u = tid + 256 * i;
            int rp = u >> 5, f4 = u & 31;
            u32 h0, l0, h1, l1;
            cvt_split(wv0[i].x, wv0[i].y, h0, l0);
            cvt_split(wv0[i].z, wv0[i].w, h1, l1);
            *(uint2*)&sBhi[2 * rp][2 * f4] = make_uint2(h0, h1);
            *(uint2*)&sBlo[2 * rp][2 * f4] = make_uint2(l0, l1);
            cvt_split(wv1[i].x, wv1[i].y, h0, l0);
            cvt_split(wv1[i].z, wv1[i].w, h1, l1);
            *(uint2*)&sBhi[2 * rp + 1][2 * f4] = make_uint2(h0, h1);
            *(uint2*)&sBlo[2 * rp + 1][2 * f4] = make_uint2(l0, l1);
        }
        if (tid < 200) {
            u32 h0, l0, h1, l1;
            cvt_split(av.x, av.y, h0, l0);
            cvt_split(av.z, av.w, h1, l1);
            *(uint2*)&sAhi[ac][akq * 2] = make_uint2(h0, h1);
            *(uint2*)&sAlo[ac][akq * 2] = make_uint2(l0, l1);
        }
        __syncthreads();
        if (ch + 1 < K1CH) {
            int h0 = hbase + (ch + 1) * 32;
#pragma unroll
            for (int i = 0; i < 2; i++) {
                int u = tid + 256 * i;
                int rp = u >> 5, f4 = u & 31;
                const float* p = W1 + (size_t)(h0 + 2 * rp) * KD + dbase + 4 * f4;
                wv0[i] = *(const float4*)p;
                wv1[i] = *(const float4*)(p + KD);
            }
            if (tid < 200) av = *(const float4*)(asrc + h0 + akq * 4);
        }
#pragma unroll
        for (int kk = 0; kk < 2; kk++) {
            u32 ko = kk * 32;
            u32 kob = kk * BKO;
            u32 ah[8], al[8], bh[4], bl[4];
            ldsm_x4(ah,     aHi + ko);
            ldsm_x4(ah + 4, aHi + AT + ko);
            ldsm_x4(al,     aLo + ko);
            ldsm_x4(al + 4, aLo + AT + ko);
            ldsm_x4_t(bh, bHi + kob);
            ldsm_x4_t(bl, bLo + kob);
#pragma unroll
            for (int mt = 0; mt < 2; mt++)
#pragma unroll
                for (int nt = 0; nt < 2; nt++)
                    mma_bf16(acc[mt][nt][0], acc[mt][nt][1], acc[mt][nt][2], acc[mt][nt][3],
                             ah[4 * mt], ah[4 * mt + 1], ah[4 * mt + 2], ah[4 * mt + 3],
                             bh[2 * nt], bh[2 * nt + 1]);
#pragma unroll
            for (int mt = 0; mt < 2; mt++)
#pragma unroll
                for (int nt = 0; nt < 2; nt++)
                    mma_bf16(acc[mt][nt][0], acc[mt][nt][1], acc[mt][nt][2], acc[mt][nt][3],
                             ah[4 * mt], ah[4 * mt + 1], ah[4 * mt + 2], ah[4 * mt + 3],
                             bl[2 * nt], bl[2 * nt + 1]);
#pragma unroll
            for (int mt = 0; mt < 2; mt++)
#pragma unroll
                for (int nt = 0; nt < 2; nt++)
                    mma_bf16(acc[mt][nt][0], acc[mt][nt][1], acc[mt][nt][2], acc[mt][nt][3],
                             al[4 * mt], al[4 * mt + 1], al[4 * mt + 2], al[4 * mt + 3],
                             bh[2 * nt], bh[2 * nt + 1]);
        }
    }

    float* gM = g_Mpart[blockIdx.y];
#pragma unroll
    for (int mt = 0; mt < 2; mt++) {
#pragma unroll
        for (int nt = 0; nt < 2; nt++) {
            int c0 = mt * 16 + g;
            int d0 = dbase + w * 16 + nt * 8 + t * 2;
            if (c0 < NOUT) {
                gM[(size_t)c0 * KD + d0]     = acc[mt][nt][0];
                gM[(size_t)c0 * KD + d0 + 1] = acc[mt][nt][1];
            }
            if (c0 + 8 < NOUT) {
                gM[(size_t)(c0 + 8) * KD + d0]     = acc[mt][nt][2];
                gM[(size_t)(c0 + 8) * KD + d0 + 1] = acc[mt][nt][3];
            }
        }
    }
}

// ---------------- k2: logits partials via HMMA + ldmatrix (validated R13) ----------------
__global__ __launch_bounds__(256, 2) void k2_tensor(const float* __restrict__ feats) {
    __shared__ u32 sAhi[128][20], sAlo[128][20];
    __shared__ u32 sBhi[32][20],  sBlo[32][20];
    int tid = threadIdx.x, w = tid >> 5, lane = tid & 31;
    int g = lane >> 2, t = lane & 3;
    int rowbase = blockIdx.x * 128;
    int kstart = blockIdx.y * KPER2;

    if (tid < 7 * 20) {
        sBhi[25 + tid / 20][tid % 20] = 0u;
        sBlo[25 + tid / 20][tid % 20] = 0u;
    }

    u32 aHi = smem_u32(&sAhi[w * 16 + (lane & 15)][(lane >> 4) * 4]);
    u32 aLo = smem_u32(&sAlo[w * 16 + (lane & 15)][(lane >> 4) * 4]);
    int bn = ((lane >> 4) << 3) + (lane & 7);
    int bwo = ((lane >> 3) & 1) * 4;
    u32 bHi = smem_u32(&sBhi[bn][bwo]);
    u32 bLo = smem_u32(&sBlo[bn][bwo]);
    const u32 BT = 16 * 20 * 4;

    float acc[4][4];
#pragma unroll
    for (int nt = 0; nt < 4; nt++)
#pragma unroll
        for (int j = 0; j < 4; j++) acc[nt][j] = 0.f;

    float4 fa[4], fb0, fb1;
    {
#pragma unroll
        for (int i = 0; i < 4; i++) {
            int u = tid + 256 * i;
            fa[i] = *(const float4*)(feats + (size_t)(rowbase + (u >> 3)) * KD + kstart + (u & 7) * 4);
        }
        if (tid < 200) {
            size_t off = (size_t)(tid >> 3) * KD + kstart + (tid & 7) * 4;
            fb0 = *(const float4*)(g_Mpart[0] + off);
            fb1 = *(const float4*)(g_Mpart[1] + off);
        }
    }

    for (int ch = 0; ch < K2CH; ch++) {
        __syncthreads();
#pragma unroll
        for (int i = 0; i < 4; i++) {
            int u = tid + 256 * i, row = u >> 3, kq = u & 7;
            u32 h0, l0, h1, l1;
            cvt_split(fa[i].x, fa[i].y, h0, l0);
            cvt_split(fa[i].z, fa[i].w, h1, l1);
            sAhi[row][kq * 2] = h0; sAhi[row][kq * 2 + 1] = h1;
            sAlo[row][kq * 2] = l0; sAlo[row][kq * 2 + 1] = l1;
        }
        if (tid < 200) {
            int c = tid >> 3, kq = tid & 7;
            u32 h0, l0, h1, l1;
            cvt_split(fb0.x + fb1.x, fb0.y + fb1.y, h0, l0);
            cvt_split(fb0.z + fb1.z, fb0.w + fb1.w, h1, l1);
            sBhi[c][kq * 2] = h0; sBhi[c][kq * 2 + 1] = h1;
            sBlo[c][kq * 2] = l0; sBlo[c][kq * 2 + 1] = l1;
        }
        __syncthreads();
        if (ch + 1 < K2CH) {
            int k0 = kstart + (ch + 1) * 32;
#pragma unroll
            for (int i = 0; i < 4; i++) {
                int u = tid + 256 * i;
                fa[i] = *(const float4*)(feats + (size_t)(rowbase + (u >> 3)) * KD + k0 + (u & 7) * 4);
            }
            if (tid < 200) {
                size_t off = (size_t)(tid >> 3) * KD + k0 + (tid & 7) * 4;
                fb0 = *(const float4*)(g_Mpart[0] + off);
                fb1 = *(const float4*)(g_Mpart[1] + off);
            }
        }
#pragma unroll
        for (int kk = 0; kk < 2; kk++) {
            u32 ko = kk * 32;
            u32 ah[4], al[4], bh[8], bl[8];
            ldsm_x4(ah, aHi + ko);
            ldsm_x4(al, aLo + ko);
            ldsm_x4(bh,     bHi + ko);
            ldsm_x4(bh + 4, bHi + BT + ko);
            ldsm_x4(bl,     bLo + ko);
            ldsm_x4(bl + 4, bLo + BT + ko);
#pragma unroll
            for (int nt = 0; nt < 4; nt++)
                mma_bf16(acc[nt][0], acc[nt][1], acc[nt][2], acc[nt][3],
                         ah[0], ah[1], ah[2], ah[3], bh[2 * nt], bh[2 * nt + 1]);
#pragma unroll
            for (int nt = 0; nt < 4; nt++)
                mma_bf16(acc[nt][0], acc[nt][1], acc[nt][2], acc[nt][3],
                         ah[0], ah[1], ah[2], ah[3], bl[2 * nt], bl[2 * nt + 1]);
#pragma unroll
            for (int nt = 0; nt < 4; nt++)
                mma_bf16(acc[nt][0], acc[nt][1], acc[nt][2], acc[nt][3],
                         al[0], al[1], al[2], al[3], bh[2 * nt], bh[2 * nt + 1]);
        }
    }

    float* gp = g_p2 + (size_t)(blockIdx.y * 16 + blockIdx.x) * 4096;
#pragma unroll
    for (int nt = 0; nt < 4; nt++) {
        int rl = w * 16 + g, c0 = nt * 8 + t * 2;
        gp[rl * 32 + c0]           = acc[nt][0];
        gp[rl * 32 + c0 + 1]       = acc[nt][1];
        gp[(rl + 8) * 32 + c0]     = acc[nt][2];
        gp[(rl + 8) * 32 + c0 + 1] = acc[nt][3];
    }
}

// ---------------- k2r: sum 28 seg partials + softmax/argmax/box decode ----------------
__global__ __launch_bounds__(256) void k2r(const float* __restrict__ props) {
    int tid = threadIdx.x, lane = tid & 31;
    int row = blockIdx.x * 8 + (tid >> 5);
    int rg = row >> 7, rl = row & 127;

    float t[NOUT];
#pragma unroll
    for (int c = 0; c < NOUT; c++) t[c] = 0.f;
    if (lane < KSPLIT2) {
        const float* base = g_p2 + (size_t)(lane * 16 + rg) * 4096 + rl * 32;
#pragma unroll
        for (int c = 0; c < NOUT; c++) t[c] = base[c];
    }
#pragma unroll
    for (int c = 0; c < NOUT; c++) {
#pragma unroll
        for (int o = 16; o > 0; o >>= 1) t[c] += __shfl_xor_sync(0xffffffffu, t[c], o);
    }

    if (lane == 0) {
#pragma unroll
        for (int c = 0; c < NOUT; c++) t[c] += g_biasf[c];
        float m = t[0]; int idx = 0;
#pragma unroll
        for (int c = 1; c < NCLS_; c++) { if (t[c] > m) { m = t[c]; idx = c; } }
        float ssum = 0.f;
#pragma unroll
        for (int c = 0; c < NCLS_; c++) ssum += expf(t[c] - m);
        float score = 1.f / ssum;
        bool valid = (idx != 0) && (score >= 0.01f);
        float p0 = props[row * 4 + 0], p1 = props[row * 4 + 1];
        float p2 = props[row * 4 + 2], p3 = props[row * 4 + 3];
        g_score[row] = valid ? score : 0.f;
        g_boxes[row * 4 + 0] = p0 + p2 * t[NCLS_ + 0];
        g_boxes[row * 4 + 1] = p1 + p3 * t[NCLS_ + 1];
        g_boxes[row * 4 + 2] = p2 * expf(t[NCLS_ + 2]);
        g_boxes[row * 4 + 3] = p3 * expf(t[NCLS_ + 3]);
    }
}

// ---------------- k3_pre: stable rank + clip -> sorted arrays ----------------
__global__ __launch_bounds__(512) void k3_pre() {
    __shared__ float sraw[512];
    int b = blockIdx.x, t = threadIdx.x;
    int gi = b * 512 + t;
    float sc = g_score[gi];
    sraw[t] = sc;
    float bx = g_boxes[gi * 4 + 0], by = g_boxes[gi * 4 + 1];
    float bw = g_boxes[gi * 4 + 2], bh = g_boxes[gi * 4 + 3];
    __syncthreads();

    int r = 0;
    for (int i = 0; i < 512; i++) {
        float si = sraw[i];
        r += (si > sc) || (si == sc && i < t);
    }

    float x0 = fminf(fmaxf(bx, 0.f), 599.f);
    float y0 = fminf(fmaxf(by, 0.f), 599.f);
    float x1 = fminf(fmaxf(bx + bw - 1.f, 0.f), 599.f);
    float y1 = fminf(fmaxf(by + bh - 1.f, 0.f), 599.f);
    float area = fmaxf(x1 - x0 + 1.f, 0.f) * fmaxf(y1 - y0 + 1.f, 0.f);

    g_ns[b][r] = sc;
    g_nx0[b][r] = x0; g_ny0[b][r] = y0;
    g_nx1[b][r] = x1; g_ny1[b][r] = y1;
    g_na[b][r] = area;
    g_nord[b][r] = (short)t;
}

// ---------------- k3a: IoU bitmask matrix via ballot ----------------
// grid (8 colchunks, 4 batches), 256 thr = 8 warps; warp handles rows w, w+8, ...
__global__ __launch_bounds__(256) void k3a() {
    __shared__ float sx0[512], sy0[512], sx1[512], sy1[512], sa[512];
    int b = blockIdx.y, cx = blockIdx.x;
    int tid = threadIdx.x, w = tid >> 5, lane = tid & 31;
    for (int i = tid; i < 512; i += 256) {
        sx0[i] = g_nx0[b][i]; sy0[i] = g_ny0[b][i];
        sx1[i] = g_nx1[b][i]; sy1[i] = g_ny1[b][i];
        sa[i] = g_na[b][i];
    }
    __syncthreads();
    int colbase = cx * 64;
    for (int i = w; i < 512; i += 8) {
        float ix0 = sx0[i], iy0 = sy0[i], ix1 = sx1[i], iy1 = sy1[i], ia = sa[i];
        u32 words[2];
#pragma unroll
        for (int hh = 0; hh < 2; hh++) {
            int c = colbase + hh * 32 + lane;
            float xx0 = fmaxf(ix0, sx0[c]);
            float yy0 = fmaxf(iy0, sy0[c]);
            float xx1 = fminf(ix1, sx1[c]);
            float yy1 = fminf(iy1, sy1[c]);
            float inter = fmaxf(xx1 - xx0 + 1.f, 0.f) * fmaxf(yy1 - yy0 + 1.f, 0.f);
            float iou = inter / (ia + sa[c] - inter + 1e-9f);
            bool bit = (iou > 0.5f) && (c != i);
            words[hh] = __ballot_sync(0xffffffffu, bit);
        }
        if (lane == 0) {
            g_mask[b][i][2 * cx]     = words[0];
            g_mask[b][i][2 * cx + 1] = words[1];
        }
    }
}

// ---------------- k3b: barrier-free serial scan (1 warp) + outputs ----------------
__global__ __launch_bounds__(512) void k3b(float* __restrict__ out) {
    __shared__ __align__(16) u32 smask[512][16];   // 32 KB
    __shared__ float ss[512];
    __shared__ short sord_[512];
    __shared__ u32 sRem[16];
    int b = blockIdx.x, t = threadIdx.x;

    {
        const uint4* mp = (const uint4*)g_mask[b][t];
        uint4* sp = (uint4*)smask[t];
        sp[0] = mp[0]; sp[1] = mp[1]; sp[2] = mp[2]; sp[3] = mp[3];
    }
    ss[t] = g_ns[b][t];
    sord_[t] = g_nord[b][t];
    __syncthreads();

    if (t < 32) {
        u32 rem = 0;
        for (int i = 0; i < 512; i++) {
            u32 wv = __shfl_sync(0xffffffffu, rem, i >> 5);
            bool rem_i = (wv >> (i & 31)) & 1u;
            bool alive = (!rem_i) && (ss[i] > 0.f);
            if (alive && t < 16) rem |= smask[i][t];
        }
        if (t < 16) sRem[t] = rem;
    }
    __syncthreads();

    bool keep = !((sRem[t >> 5] >> (t & 31)) & 1u) && (ss[t] > 0.f);
    int orig = sord_[t];
    int go = b * 512 + orig;

    out[go] = keep ? ss[t] : 0.f;

    float obx = g_boxes[go * 4 + 0], oby = g_boxes[go * 4 + 1];
    float obw = g_boxes[go * 4 + 2], obh = g_boxes[go * 4 + 3];
    float* ob = out + NROI + (size_t)go * 4;
    if (keep) {
        ob[0] = obx; ob[1] = oby;
        ob[2] = obx + obw - 1.f;
        ob[3] = oby + obh - 1.f;
    } else {
        ob[0] = 0.f; ob[1] = 0.f; ob[2] = -1.f; ob[3] = -1.f;
    }
}

extern "C" void kernel_launch(void* const* d_in, const int* in_sizes, int n_in,
                              void* d_out, int out_size) {
    (void)in_sizes; (void)n_in; (void)out_size;
    const float* rois  = (const float*)d_in[0];
    const float* props = (const float*)d_in[1];
    const float* W1    = (const float*)d_in[2];
    const float* b1    = (const float*)d_in[3];
    const float* Wc    = (const float*)d_in[4];
    const float* bc    = (const float*)d_in[5];
    const float* Wr    = (const float*)d_in[6];
    const float* br    = (const float*)d_in[7];
    float* out = (float*)d_out;

    k_bias<<<NOUT, 256>>>(b1, Wc, bc, Wr, br);               // launch 1
    k1_tensor<<<dim3(KD / 128, HSPL), 256>>>(W1, Wc, Wr);    // launch 2
    k_dummy<<<1, 32>>>();                                    // launch 3
    k2_tensor<<<dim3(16, KSPLIT2), 256>>>(rois);             // launch 4 -> ncu captures k2
    k2r<<<NROI / 8, 256>>>(props);                           // launch 5
    k3_pre<<<4, 512>>>();                                    // launch 6
    k3a<<<dim3(8, 4), 256>>>();                              // launch 7
    k3b<<<4, 512>>>(out);                                    // launch 8
}

// round 16
// speedup vs baseline: 2.0903x; 1.0066x over previous
#include <cuda_runtime.h>
#include <cuda_bf16.h>
#include <cstdint>

typedef unsigned long long u64;
typedef unsigned int u32;

#define KD 25088
#define KH 4096
#define NROI 2048
#define NOUT 25
#define NCLS_ 21
#define KSPLIT2 28
#define KPER2 (KD / KSPLIT2)      // 896
#define K2CH (KPER2 / 32)         // 28
#define HSPL 2
#define KHPER (KH / HSPL)         // 2048
#define K1CH (KHPER / 32)         // 64

// ---- mma.sync m16n8k16 bf16 (validated; rel_err ~1e-5) ----
__device__ __forceinline__ void mma_bf16(float& d0, float& d1, float& d2, float& d3,
                                         u32 a0, u32 a1, u32 a2, u32 a3,
                                         u32 b0, u32 b1) {
    asm volatile(
        "mma.sync.aligned.m16n8k16.row.col.f32.bf16.bf16.f32 "
        "{%0,%1,%2,%3}, {%4,%5,%6,%7}, {%8,%9}, {%0,%1,%2,%3};"
        : "+f"(d0), "+f"(d1), "+f"(d2), "+f"(d3)
        : "r"(a0), "r"(a1), "r"(a2), "r"(a3), "r"(b0), "r"(b1));
}

__device__ __forceinline__ void ldsm_x4(u32* r, u32 addr) {
    asm volatile("ldmatrix.sync.aligned.m8n8.x4.shared.b16 {%0,%1,%2,%3}, [%4];"
        : "=r"(r[0]), "=r"(r[1]), "=r"(r[2]), "=r"(r[3]) : "r"(addr));
}
__device__ __forceinline__ void ldsm_x4_t(u32* r, u32 addr) {
    asm volatile("ldmatrix.sync.aligned.m8n8.x4.trans.shared.b16 {%0,%1,%2,%3}, [%4];"
        : "=r"(r[0]), "=r"(r[1]), "=r"(r[2]), "=r"(r[3]) : "r"(addr));
}

__device__ __forceinline__ u32 smem_u32(const void* p) {
    u32 a;
    asm("{ .reg .u64 t; cvta.to.shared.u64 t, %1; cvt.u32.u64 %0, t; }" : "=r"(a) : "l"(p));
    return a;
}

__device__ __forceinline__ void cvt_split(float x, float y, u32& hi, u32& lo) {
    asm("cvt.rn.bf16x2.f32 %0, %1, %2;" : "=r"(hi) : "f"(y), "f"(x));
    float rx = x - __uint_as_float(hi << 16);
    float ry = y - __uint_as_float(hi & 0xFFFF0000u);
    asm("cvt.rn.bf16x2.f32 %0, %1, %2;" : "=r"(lo) : "f"(ry), "f"(rx));
}

// scratch
__device__ __align__(16) float g_Mpart[HSPL][NOUT * KD];                // 5 MB
__device__ __align__(16) float g_p2[(size_t)KSPLIT2 * 16 * 128 * 32];   // 7 MB
__device__ float g_biasf[NOUT];
__device__ float g_score[NROI];
__device__ __align__(16) float g_boxes[NROI * 4];
// NMS scratch
__device__ float g_ns[4][512];
__device__ float g_nx0[4][512], g_ny0[4][512], g_nx1[4][512], g_ny1[4][512], g_na[4][512];
__device__ short g_nord[4][512];
__device__ __align__(16) u32 g_mask[4][512][16];

__global__ void k_dummy() {}

// ---------------- fused bias ----------------
__global__ void k_bias(const float* __restrict__ b1, const float* __restrict__ Wc,
                       const float* __restrict__ bc, const float* __restrict__ Wr,
                       const float* __restrict__ br) {
    int c = blockIdx.x;
    int tid = threadIdx.x;
    const float* p = (c < NCLS_) ? (Wc + (size_t)c * KH) : (Wr + (size_t)(c - NCLS_) * KH);
    float s = 0.f;
    for (int h = tid; h < KH; h += 256) s += b1[h] * p[h];
    __shared__ float red[256];
    red[tid] = s;
    __syncthreads();
    for (int o = 128; o > 0; o >>= 1) {
        if (tid < o) red[tid] += red[tid + o];
        __syncthreads();
    }
    if (tid == 0) g_biasf[c] = red[0] + ((c < NCLS_) ? bc[c] : br[c - NCLS_]);
}

// ---------------- k1: M partial = P @ W1 via HMMA, double-buffered swizzled tiles ----------------
// B: [32 k][64 words], phys_blk = blk ^ (row&7). A: [32 c][16 words], phys_blk = blk ^ ((row>>1)&3).
__global__ __launch_bounds__(256, 2) void k1_tensor(const float* __restrict__ W1,
                                                    const float* __restrict__ Wc,
                                                    const float* __restrict__ Wr) {
    __shared__ u32 sBhi[2][32][64], sBlo[2][32][64];   // 32 KB
    __shared__ u32 sAhi[2][32][16], sAlo[2][32][16];   // 8 KB
    int tid = threadIdx.x, w = tid >> 5, lane = tid & 31;
    int g = lane >> 2, t = lane & 3;
    int dbase = blockIdx.x * 128;
    int hbase = blockIdx.y * KHPER;

    // zero-pad A rows 25..31, both buffers
    if (tid < 224) {
        int bq = tid / 112, rem = tid % 112;
        int rr = 25 + rem / 16, ww = rem % 16;
        sAhi[bq][rr][ww] = 0u; sAlo[bq][rr][ww] = 0u;
    }

    float acc[2][2][4];
#pragma unroll
    for (int mt = 0; mt < 2; mt++)
#pragma unroll
        for (int nt = 0; nt < 2; nt++)
#pragma unroll
            for (int j = 0; j < 4; j++) acc[mt][nt][j] = 0.f;

    int ac = tid >> 3, akq = tid & 7;
    const float* asrc = (tid < 200)
        ? ((ac < NCLS_) ? Wc + (size_t)ac * KH : Wr + (size_t)(ac - NCLS_) * KH) : Wc;

    float4 wv0[2], wv1[2], av;

#define K1_LDG(H0)                                                                 \
    {                                                                              \
        _Pragma("unroll")                                                          \
        for (int i = 0; i < 2; i++) {                                              \
            int u = tid + 256 * i;                                                 \
            int rp = u >> 5, f4 = u & 31;                                          \
            const float* p = W1 + (size_t)((H0) + 2 * rp) * KD + dbase + 4 * f4;   \
            wv0[i] = *(const float4*)p;                                            \
            wv1[i] = *(const float4*)(p + KD);                                     \
        }                                                                          \
        if (tid < 200) av = *(const float4*)(asrc + (H0) + akq * 4);               \
    }

#define K1_CVT(BUF)                                                                \
    {                                                                              \
        _Pragma("unroll")                                                          \
        for (int i = 0; i < 2; i++) {                                              \
            int u = tid + 256 * i;                                                 \
            int rp = u >> 5, f4 = u & 31;                                          \
            int off = (2 * f4) & 3;                                                \
            u32 h0, l0, h1, l1;                                                    \
            cvt_split(wv0[i].x, wv0[i].y, h0, l0);                                 \
            cvt_split(wv0[i].z, wv0[i].w, h1, l1);                                 \
            int idx0 = (((f4 >> 1) ^ ((2 * rp) & 7)) << 2) + off;                  \
            *(uint2*)&sBhi[BUF][2 * rp][idx0] = make_uint2(h0, h1);                \
            *(uint2*)&sBlo[BUF][2 * rp][idx0] = make_uint2(l0, l1);                \
            cvt_split(wv1[i].x, wv1[i].y, h0, l0);                                 \
            cvt_split(wv1[i].z, wv1[i].w, h1, l1);                                 \
            int idx1 = (((f4 >> 1) ^ ((2 * rp + 1) & 7)) << 2) + off;              \
            *(uint2*)&sBhi[BUF][2 * rp + 1][idx1] = make_uint2(h0, h1);            \
            *(uint2*)&sBlo[BUF][2 * rp + 1][idx1] = make_uint2(l0, l1);            \
        }                                                                          \
        if (tid < 200) {                                                           \
            u32 h0, l0, h1, l1;                                                    \
            cvt_split(av.x, av.y, h0, l0);                                         \
            cvt_split(av.z, av.w, h1, l1);                                         \
            int idxa = (((akq >> 1) ^ ((ac >> 1) & 3)) << 2) + ((2 * akq) & 3);    \
            *(uint2*)&sAhi[BUF][ac][idxa] = make_uint2(h0, h1);                    \
            *(uint2*)&sAlo[BUF][ac][idxa] = make_uint2(l0, l1);                    \
        }                                                                          \
    }

    K1_LDG(hbase);
    K1_CVT(0);
    K1_LDG(hbase + 32);
    __syncthreads();

    for (int ch = 0; ch < K1CH; ch++) {
        int buf = ch & 1;
        if (ch + 1 < K1CH) K1_CVT(buf ^ 1);
        if (ch + 2 < K1CH) K1_LDG(hbase + (ch + 2) * 32);
#pragma unroll
        for (int kk = 0; kk < 2; kk++) {
            u32 ah[8], al[8], bh[4], bl[4];
            int ar = lane & 15;
            int aph = (((lane >> 4) + kk * 2) ^ ((ar >> 1) & 3)) << 2;
            ldsm_x4(ah,     smem_u32(&sAhi[buf][ar][aph]));
            ldsm_x4(ah + 4, smem_u32(&sAhi[buf][16 + ar][aph]));
            ldsm_x4(al,     smem_u32(&sAlo[buf][ar][aph]));
            ldsm_x4(al + 4, smem_u32(&sAlo[buf][16 + ar][aph]));
            int br = (lane & 15) + kk * 16;
            int bph = (((w << 1) + (lane >> 4)) ^ (lane & 7)) << 2;
            ldsm_x4_t(bh, smem_u32(&sBhi[buf][br][bph]));
            ldsm_x4_t(bl, smem_u32(&sBlo[buf][br][bph]));
#pragma unroll
            for (int mt = 0; mt < 2; mt++)
#pragma unroll
                for (int nt = 0; nt < 2; nt++)
                    mma_bf16(acc[mt][nt][0], acc[mt][nt][1], acc[mt][nt][2], acc[mt][nt][3],
                             ah[4 * mt], ah[4 * mt + 1], ah[4 * mt + 2], ah[4 * mt + 3],
                             bh[2 * nt], bh[2 * nt + 1]);
#pragma unroll
            for (int mt = 0; mt < 2; mt++)
#pragma unroll
                for (int nt = 0; nt < 2; nt++)
                    mma_bf16(acc[mt][nt][0], acc[mt][nt][1], acc[mt][nt][2], acc[mt][nt][3],
                             ah[4 * mt], ah[4 * mt + 1], ah[4 * mt + 2], ah[4 * mt + 3],
                             bl[2 * nt], bl[2 * nt + 1]);
#pragma unroll
            for (int mt = 0; mt < 2; mt++)
#pragma unroll
                for (int nt = 0; nt < 2; nt++)
                    mma_bf16(acc[mt][nt][0], acc[mt][nt][1], acc[mt][nt][2], acc[mt][nt][3],
                             al[4 * mt], al[4 * mt + 1], al[4 * mt + 2], al[4 * mt + 3],
                             bh[2 * nt], bh[2 * nt + 1]);
        }
        __syncthreads();
    }

    float* gM = g_Mpart[blockIdx.y];
#pragma unroll
    for (int mt = 0; mt < 2; mt++) {
#pragma unroll
        for (int nt = 0; nt < 2; nt++) {
            int c0 = mt * 16 + g;
            int d0 = dbase + w * 16 + nt * 8 + t * 2;
            if (c0 < NOUT) {
                gM[(size_t)c0 * KD + d0]     = acc[mt][nt][0];
                gM[(size_t)c0 * KD + d0 + 1] = acc[mt][nt][1];
            }
            if (c0 + 8 < NOUT) {
                gM[(size_t)(c0 + 8) * KD + d0]     = acc[mt][nt][2];
                gM[(size_t)(c0 + 8) * KD + d0 + 1] = acc[mt][nt][3];
            }
        }
    }
}

// ---------------- k2: logits partials via HMMA, double-buffered swizzled tiles ----------------
// A: [128 row][16 words], B: [32 c][16 words]; phys_blk = blk ^ ((row>>1)&3).
__global__ __launch_bounds__(256, 2) void k2_tensor(const float* __restrict__ feats) {
    __shared__ u32 sAhi[2][128][16], sAlo[2][128][16];   // 32 KB
    __shared__ u32 sBhi[2][32][16],  sBlo[2][32][16];    // 8 KB
    int tid = threadIdx.x, w = tid >> 5, lane = tid & 31;
    int g = lane >> 2, t = lane & 3;
    int rowbase = blockIdx.x * 128;
    int kstart = blockIdx.y * KPER2;

    if (tid < 224) {     // zero-pad B rows 25..31, both buffers
        int bq = tid / 112, rem = tid % 112;
        int rr = 25 + rem / 16, ww = rem % 16;
        sBhi[bq][rr][ww] = 0u; sBlo[bq][rr][ww] = 0u;
    }

    float acc[4][4];
#pragma unroll
    for (int nt = 0; nt < 4; nt++)
#pragma unroll
        for (int j = 0; j < 4; j++) acc[nt][j] = 0.f;

    float4 fa[4], fb0, fb1;

#define K2_LDG(K0)                                                                   \
    {                                                                                \
        _Pragma("unroll")                                                            \
        for (int i = 0; i < 4; i++) {                                                \
            int u = tid + 256 * i;                                                   \
            fa[i] = *(const float4*)(feats + (size_t)(rowbase + (u >> 3)) * KD + (K0) + (u & 7) * 4); \
        }                                                                            \
        if (tid < 200) {                                                             \
            size_t off = (size_t)(tid >> 3) * KD + (K0) + (tid & 7) * 4;             \
            fb0 = *(const float4*)(g_Mpart[0] + off);                                \
            fb1 = *(const float4*)(g_Mpart[1] + off);                                \
        }                                                                            \
    }

#define K2_CVT(BUF)                                                                 \
    {                                                                               \
        _Pragma("unroll")                                                           \
        for (int i = 0; i < 4; i++) {                                               \
            int u = tid + 256 * i, row = u >> 3, kq = u & 7;                        \
            u32 h0, l0, h1, l1;                                                     \
            cvt_split(fa[i].x, fa[i].y, h0, l0);                                    \
            cvt_split(fa[i].z, fa[i].w, h1, l1);                                    \
            int idx = (((kq >> 1) ^ ((row >> 1) & 3)) << 2) + ((2 * kq) & 3);       \
            *(uint2*)&sAhi[BUF][row][idx] = make_uint2(h0, h1);                     \
            *(uint2*)&sAlo[BUF][row][idx] = make_uint2(l0, l1);                     \
        }                                                                           \
        if (tid < 200) {                                                            \
            int c = tid >> 3, kq = tid & 7;                                         \
            u32 h0, l0, h1, l1;                                                     \
            cvt_split(fb0.x + fb1.x, fb0.y + fb1.y, h0, l0);                        \
            cvt_split(fb0.z + fb1.z, fb0.w + fb1.w, h1, l1);                        \
            int idx = (((kq >> 1) ^ ((c >> 1) & 3)) << 2) + ((2 * kq) & 3);         \
            *(uint2*)&sBhi[BUF][c][idx] = make_uint2(h0, h1);                       \
            *(uint2*)&sBlo[BUF][c][idx] = make_uint2(l0, l1);                       \
        }                                                                           \
    }

    K2_LDG(kstart);
    K2_CVT(0);
    K2_LDG(kstart + 32);
    __syncthreads();

    for (int ch = 0; ch < K2CH; ch++) {
        int buf = ch & 1;
        if (ch + 1 < K2CH) K2_CVT(buf ^ 1);
        if (ch + 2 < K2CH) K2_LDG(kstart + (ch + 2) * 32);
#pragma unroll
        for (int kk = 0; kk < 2; kk++) {
            u32 ah[4], al[4], bh[8], bl[8];
            int ar = w * 16 + (lane & 15);
            int aph = (((lane >> 4) + kk * 2) ^ ((ar >> 1) & 3)) << 2;
            ldsm_x4(ah, smem_u32(&sAhi[buf][ar][aph]));
            ldsm_x4(al, smem_u32(&sAlo[buf][ar][aph]));
            int bn = ((lane >> 4) << 3) + (lane & 7);
            int bph = ((((lane >> 3) & 1) + kk * 2) ^ ((bn >> 1) & 3)) << 2;
            ldsm_x4(bh,     smem_u32(&sBhi[buf][bn][bph]));
            ldsm_x4(bh + 4, smem_u32(&sBhi[buf][bn + 16][bph]));
            ldsm_x4(bl,     smem_u32(&sBlo[buf][bn][bph]));
            ldsm_x4(bl + 4, smem_u32(&sBlo[buf][bn + 16][bph]));
#pragma unroll
            for (int nt = 0; nt < 4; nt++)
                mma_bf16(acc[nt][0], acc[nt][1], acc[nt][2], acc[nt][3],
                         ah[0], ah[1], ah[2], ah[3], bh[2 * nt], bh[2 * nt + 1]);
#pragma unroll
            for (int nt = 0; nt < 4; nt++)
                mma_bf16(acc[nt][0], acc[nt][1], acc[nt][2], acc[nt][3],
                         ah[0], ah[1], ah[2], ah[3], bl[2 * nt], bl[2 * nt + 1]);
#pragma unroll
            for (int nt = 0; nt < 4; nt++)
                mma_bf16(acc[nt][0], acc[nt][1], acc[nt][2], acc[nt][3],
                         al[0], al[1], al[2], al[3], bh[2 * nt], bh[2 * nt + 1]);
        }
        __syncthreads();
    }

    float* gp = g_p2 + (size_t)(blockIdx.y * 16 + blockIdx.x) * 4096;
#pragma unroll
    for (int nt = 0; nt < 4; nt++) {
        int rl = w * 16 + g, c0 = nt * 8 + t * 2;
        gp[rl * 32 + c0]           = acc[nt][0];
        gp[rl * 32 + c0 + 1]       = acc[nt][1];
        gp[(rl + 8) * 32 + c0]     = acc[nt][2];
        gp[(rl + 8) * 32 + c0 + 1] = acc[nt][3];
    }
}

// ---------------- k2r: sum 28 seg partials + softmax/argmax/box decode ----------------
__global__ __launch_bounds__(256) void k2r(const float* __restrict__ props) {
    int tid = threadIdx.x, lane = tid & 31;
    int row = blockIdx.x * 8 + (tid >> 5);
    int rg = row >> 7, rl = row & 127;

    float t[NOUT];
#pragma unroll
    for (int c = 0; c < NOUT; c++) t[c] = 0.f;
    if (lane < KSPLIT2) {
        const float* base = g_p2 + (size_t)(lane * 16 + rg) * 4096 + rl * 32;
#pragma unroll
        for (int c = 0; c < NOUT; c++) t[c] = base[c];
    }
#pragma unroll
    for (int c = 0; c < NOUT; c++) {
#pragma unroll
        for (int o = 16; o > 0; o >>= 1) t[c] += __shfl_xor_sync(0xffffffffu, t[c], o);
    }

    if (lane == 0) {
#pragma unroll
        for (int c = 0; c < NOUT; c++) t[c] += g_biasf[c];
        float m = t[0]; int idx = 0;
#pragma unroll
        for (int c = 1; c < NCLS_; c++) { if (t[c] > m) { m = t[c]; idx = c; } }
        float ssum = 0.f;
#pragma unroll
        for (int c = 0; c < NCLS_; c++) ssum += expf(t[c] - m);
        float score = 1.f / ssum;
        bool valid = (idx != 0) && (score >= 0.01f);
        float p0 = props[row * 4 + 0], p1 = props[row * 4 + 1];
        float p2 = props[row * 4 + 2], p3 = props[row * 4 + 3];
        g_score[row] = valid ? score : 0.f;
        g_boxes[row * 4 + 0] = p0 + p2 * t[NCLS_ + 0];
        g_boxes[row * 4 + 1] = p1 + p3 * t[NCLS_ + 1];
        g_boxes[row * 4 + 2] = p2 * expf(t[NCLS_ + 2]);
        g_boxes[row * 4 + 3] = p3 * expf(t[NCLS_ + 3]);
    }
}

// ---------------- k3_pre: stable rank + clip -> sorted arrays ----------------
__global__ __launch_bounds__(512) void k3_pre() {
    __shared__ float sraw[512];
    int b = blockIdx.x, t = threadIdx.x;
    int gi = b * 512 + t;
    float sc = g_score[gi];
    sraw[t] = sc;
    float bx = g_boxes[gi * 4 + 0], by = g_boxes[gi * 4 + 1];
    float bw = g_boxes[gi * 4 + 2], bh = g_boxes[gi * 4 + 3];
    __syncthreads();

    int r = 0;
    for (int i = 0; i < 512; i++) {
        float si = sraw[i];
        r += (si > sc) || (si == sc && i < t);
    }

    float x0 = fminf(fmaxf(bx, 0.f), 599.f);
    float y0 = fminf(fmaxf(by, 0.f), 599.f);
    float x1 = fminf(fmaxf(bx + bw - 1.f, 0.f), 599.f);
    float y1 = fminf(fmaxf(by + bh - 1.f, 0.f), 599.f);
    float area = fmaxf(x1 - x0 + 1.f, 0.f) * fmaxf(y1 - y0 + 1.f, 0.f);

    g_ns[b][r] = sc;
    g_nx0[b][r] = x0; g_ny0[b][r] = y0;
    g_nx1[b][r] = x1; g_ny1[b][r] = y1;
    g_na[b][r] = area;
    g_nord[b][r] = (short)t;
}

// ---------------- k3a: IoU bitmask matrix via ballot ----------------
__global__ __launch_bounds__(256) void k3a() {
    __shared__ float sx0[512], sy0[512], sx1[512], sy1[512], sa[512];
    int b = blockIdx.y, cx = blockIdx.x;
    int tid = threadIdx.x, w = tid >> 5, lane = tid & 31;
    for (int i = tid; i < 512; i += 256) {
        sx0[i] = g_nx0[b][i]; sy0[i] = g_ny0[b][i];
        sx1[i] = g_nx1[b][i]; sy1[i] = g_ny1[b][i];
        sa[i] = g_na[b][i];
    }
    __syncthreads();
    int colbase = cx * 64;
    for (int i = w; i < 512; i += 8) {
        float ix0 = sx0[i], iy0 = sy0[i], ix1 = sx1[i], iy1 = sy1[i], ia = sa[i];
        u32 words[2];
#pragma unroll
        for (int hh = 0; hh < 2; hh++) {
            int c = colbase + hh * 32 + lane;
            float xx0 = fmaxf(ix0, sx0[c]);
            float yy0 = fmaxf(iy0, sy0[c]);
            float xx1 = fminf(ix1, sx1[c]);
            float yy1 = fminf(iy1, sy1[c]);
            float inter = fmaxf(xx1 - xx0 + 1.f, 0.f) * fmaxf(yy1 - yy0 + 1.f, 0.f);
            float iou = inter / (ia + sa[c] - inter + 1e-9f);
            bool bit = (iou > 0.5f) && (c != i);
            words[hh] = __ballot_sync(0xffffffffu, bit);
        }
        if (lane == 0) {
            g_mask[b][i][2 * cx]     = words[0];
            g_mask[b][i][2 * cx + 1] = words[1];
        }
    }
}

// ---------------- k3b: barrier-free serial scan (1 warp) + outputs ----------------
__global__ __launch_bounds__(512) void k3b(float* __restrict__ out) {
    __shared__ __align__(16) u32 smask[512][16];
    __shared__ float ss[512];
    __shared__ short sord_[512];
    __shared__ u32 sRem[16];
    int b = blockIdx.x, t = threadIdx.x;

    {
        const uint4* mp = (const uint4*)g_mask[b][t];
        uint4* sp = (uint4*)smask[t];
        sp[0] = mp[0]; sp[1] = mp[1]; sp[2] = mp[2]; sp[3] = mp[3];
    }
    ss[t] = g_ns[b][t];
    sord_[t] = g_nord[b][t];
    __syncthreads();

    if (t < 32) {
        u32 rem = 0;
        for (int i = 0; i < 512; i++) {
            u32 wv = __shfl_sync(0xffffffffu, rem, i >> 5);
            bool rem_i = (wv >> (i & 31)) & 1u;
            bool alive = (!rem_i) && (ss[i] > 0.f);
            if (alive && t < 16) rem |= smask[i][t];
        }
        if (t < 16) sRem[t] = rem;
    }
    __syncthreads();

    bool keep = !((sRem[t >> 5] >> (t & 31)) & 1u) && (ss[t] > 0.f);
    int orig = sord_[t];
    int go = b * 512 + orig;

    out[go] = keep ? ss[t] : 0.f;

    float obx = g_boxes[go * 4 + 0], oby = g_boxes[go * 4 + 1];
    float obw = g_boxes[go * 4 + 2], obh = g_boxes[go * 4 + 3];
    float* ob = out + NROI + (size_t)go * 4;
    if (keep) {
        ob[0] = obx; ob[1] = oby;
        ob[2] = obx + obw - 1.f;
        ob[3] = oby + obh - 1.f;
    } else {
        ob[0] = 0.f; ob[1] = 0.f; ob[2] = -1.f; ob[3] = -1.f;
    }
}

extern "C" void kernel_launch(void* const* d_in, const int* in_sizes, int n_in,
                              void* d_out, int out_size) {
    (void)in_sizes; (void)n_in; (void)out_size;
    const float* rois  = (const float*)d_in[0];
    const float* props = (const float*)d_in[1];
    const float* W1    = (const float*)d_in[2];
    const float* b1    = (const float*)d_in[3];
    const float* Wc    = (const float*)d_in[4];
    const float* bc    = (const float*)d_in[5];
    const float* Wr    = (const float*)d_in[6];
    const float* br    = (const float*)d_in[7];
    float* out = (float*)d_out;

    k_bias<<<NOUT, 256>>>(b1, Wc, bc, Wr, br);               // launch 1
    k1_tensor<<<dim3(KD / 128, HSPL), 256>>>(W1, Wc, Wr);    // launch 2
    k_dummy<<<1, 32>>>();                                    // launch 3
    k2_tensor<<<dim3(16, KSPLIT2), 256>>>(rois);             // launch 4 -> ncu captures k2
    k2r<<<NROI / 8, 256>>>(props);                           // launch 5
    k3_pre<<<4, 512>>>();                                    // launch 6
    k3a<<<dim3(8, 4), 256>>>();                              // launch 7
    k3b<<<4, 512>>>(out);                                    // launch 8
}

// round 17
// speedup vs baseline: 2.2207x; 1.0624x over previous
#include <cuda_runtime.h>
#include <cuda_bf16.h>
#include <cstdint>

typedef unsigned long long u64;
typedef unsigned int u32;

#define KD 25088
#define KH 4096
#define NROI 2048
#define NOUT 25
#define NCLS_ 21
#define KSPLIT2 28
#define KPER2 (KD / KSPLIT2)      // 896
#define K2CH (KPER2 / 32)         // 28
#define HSPL 2
#define KHPER (KH / HSPL)         // 2048
#define K1CH (KHPER / 32)         // 64

// ---- mma.sync m16n8k16 bf16 (validated; rel_err ~1e-5) ----
__device__ __forceinline__ void mma_bf16(float& d0, float& d1, float& d2, float& d3,
                                         u32 a0, u32 a1, u32 a2, u32 a3,
                                         u32 b0, u32 b1) {
    asm volatile(
        "mma.sync.aligned.m16n8k16.row.col.f32.bf16.bf16.f32 "
        "{%0,%1,%2,%3}, {%4,%5,%6,%7}, {%8,%9}, {%0,%1,%2,%3};"
        : "+f"(d0), "+f"(d1), "+f"(d2), "+f"(d3)
        : "r"(a0), "r"(a1), "r"(a2), "r"(a3), "r"(b0), "r"(b1));
}

__device__ __forceinline__ void ldsm_x4(u32* r, u32 addr) {
    asm volatile("ldmatrix.sync.aligned.m8n8.x4.shared.b16 {%0,%1,%2,%3}, [%4];"
        : "=r"(r[0]), "=r"(r[1]), "=r"(r[2]), "=r"(r[3]) : "r"(addr));
}
__device__ __forceinline__ void ldsm_x4_t(u32* r, u32 addr) {
    asm volatile("ldmatrix.sync.aligned.m8n8.x4.trans.shared.b16 {%0,%1,%2,%3}, [%4];"
        : "=r"(r[0]), "=r"(r[1]), "=r"(r[2]), "=r"(r[3]) : "r"(addr));
}

__device__ __forceinline__ u32 smem_u32(const void* p) {
    u32 a;
    asm("{ .reg .u64 t; cvta.to.shared.u64 t, %1; cvt.u32.u64 %0, t; }" : "=r"(a) : "l"(p));
    return a;
}

__device__ __forceinline__ void cvt_split(float x, float y, u32& hi, u32& lo) {
    asm("cvt.rn.bf16x2.f32 %0, %1, %2;" : "=r"(hi) : "f"(y), "f"(x));
    float rx = x - __uint_as_float(hi << 16);
    float ry = y - __uint_as_float(hi & 0xFFFF0000u);
    asm("cvt.rn.bf16x2.f32 %0, %1, %2;" : "=r"(lo) : "f"(ry), "f"(rx));
}

// scratch
__device__ __align__(16) float g_Mpart[HSPL][NOUT * KD];                // 5 MB
__device__ __align__(16) float g_p2[(size_t)KSPLIT2 * 16 * 128 * 32];   // 7 MB
__device__ float g_biasf[NOUT];
__device__ float g_score[NROI];
__device__ __align__(16) float g_boxes[NROI * 4];
// NMS scratch
__device__ float g_ns[4][512];
__device__ float g_nx0[4][512], g_ny0[4][512], g_nx1[4][512], g_ny1[4][512], g_na[4][512];
__device__ short g_nord[4][512];
__device__ __align__(16) u32 g_mask[4][512][16];

__global__ void k_dummy() {}

// ---------------- fused bias ----------------
__global__ void k_bias(const float* __restrict__ b1, const float* __restrict__ Wc,
                       const float* __restrict__ bc, const float* __restrict__ Wr,
                       const float* __restrict__ br) {
    int c = blockIdx.x;
    int tid = threadIdx.x;
    const float* p = (c < NCLS_) ? (Wc + (size_t)c * KH) : (Wr + (size_t)(c - NCLS_) * KH);
    float s = 0.f;
    for (int h = tid; h < KH; h += 256) s += b1[h] * p[h];
    __shared__ float red[256];
    red[tid] = s;
    __syncthreads();
    for (int o = 128; o > 0; o >>= 1) {
        if (tid < o) red[tid] += red[tid + o];
        __syncthreads();
    }
    if (tid == 0) g_biasf[c] = red[0] + ((c < NCLS_) ? bc[c] : br[c - NCLS_]);
}

// ---------------- k1: M partial = P @ W1 via HMMA, double-buffered swizzled (best R16) ----------------
__global__ __launch_bounds__(256, 2) void k1_tensor(const float* __restrict__ W1,
                                                    const float* __restrict__ Wc,
                                                    const float* __restrict__ Wr) {
    __shared__ u32 sBhi[2][32][64], sBlo[2][32][64];   // 32 KB
    __shared__ u32 sAhi[2][32][16], sAlo[2][32][16];   // 8 KB
    int tid = threadIdx.x, w = tid >> 5, lane = tid & 31;
    int g = lane >> 2, t = lane & 3;
    int dbase = blockIdx.x * 128;
    int hbase = blockIdx.y * KHPER;

    if (tid < 224) {
        int bq = tid / 112, rem = tid % 112;
        int rr = 25 + rem / 16, ww = rem % 16;
        sAhi[bq][rr][ww] = 0u; sAlo[bq][rr][ww] = 0u;
    }

    float acc[2][2][4];
#pragma unroll
    for (int mt = 0; mt < 2; mt++)
#pragma unroll
        for (int nt = 0; nt < 2; nt++)
#pragma unroll
            for (int j = 0; j < 4; j++) acc[mt][nt][j] = 0.f;

    int ac = tid >> 3, akq = tid & 7;
    const float* asrc = (tid < 200)
        ? ((ac < NCLS_) ? Wc + (size_t)ac * KH : Wr + (size_t)(ac - NCLS_) * KH) : Wc;

    float4 wv0[2], wv1[2], av;

#define K1_LDG(H0)                                                                 \
    {                                                                              \
        _Pragma("unroll")                                                          \
        for (int i = 0; i < 2; i++) {                                              \
            int u = tid + 256 * i;                                                 \
            int rp = u >> 5, f4 = u & 31;                                          \
            const float* p = W1 + (size_t)((H0) + 2 * rp) * KD + dbase + 4 * f4;   \
            wv0[i] = *(const float4*)p;                                            \
            wv1[i] = *(const float4*)(p + KD);                                     \
        }                                                                          \
        if (tid < 200) av = *(const float4*)(asrc + (H0) + akq * 4);               \
    }

#define K1_CVT(BUF)                                                                \
    {                                                                              \
        _Pragma("unroll")                                                          \
        for (int i = 0; i < 2; i++) {                                              \
            int u = tid + 256 * i;                                                 \
            int rp = u >> 5, f4 = u & 31;                                          \
            int off = (2 * f4) & 3;                                                \
            u32 h0, l0, h1, l1;                                                    \
            cvt_split(wv0[i].x, wv0[i].y, h0, l0);                                 \
            cvt_split(wv0[i].z, wv0[i].w, h1, l1);                                 \
            int idx0 = (((f4 >> 1) ^ ((2 * rp) & 7)) << 2) + off;                  \
            *(uint2*)&sBhi[BUF][2 * rp][idx0] = make_uint2(h0, h1);                \
            *(uint2*)&sBlo[BUF][2 * rp][idx0] = make_uint2(l0, l1);                \
            cvt_split(wv1[i].x, wv1[i].y, h0, l0);                                 \
            cvt_split(wv1[i].z, wv1[i].w, h1, l1);                                 \
            int idx1 = (((f4 >> 1) ^ ((2 * rp + 1) & 7)) << 2) + off;              \
            *(uint2*)&sBhi[BUF][2 * rp + 1][idx1] = make_uint2(h0, h1);            \
            *(uint2*)&sBlo[BUF][2 * rp + 1][idx1] = make_uint2(l0, l1);            \
        }                                                                          \
        if (tid < 200) {                                                           \
            u32 h0, l0, h1, l1;                                                    \
            cvt_split(av.x, av.y, h0, l0);                                         \
            cvt_split(av.z, av.w, h1, l1);                                         \
            int idxa = (((akq >> 1) ^ ((ac >> 1) & 3)) << 2) + ((2 * akq) & 3);    \
            *(uint2*)&sAhi[BUF][ac][idxa] = make_uint2(h0, h1);                    \
            *(uint2*)&sAlo[BUF][ac][idxa] = make_uint2(l0, l1);                    \
        }                                                                          \
    }

    K1_LDG(hbase);
    K1_CVT(0);
    K1_LDG(hbase + 32);
    __syncthreads();

    for (int ch = 0; ch < K1CH; ch++) {
        int buf = ch & 1;
        if (ch + 1 < K1CH) K1_CVT(buf ^ 1);
        if (ch + 2 < K1CH) K1_LDG(hbase + (ch + 2) * 32);
#pragma unroll
        for (int kk = 0; kk < 2; kk++) {
            u32 ah[8], al[8], bh[4], bl[4];
            int ar = lane & 15;
            int aph = (((lane >> 4) + kk * 2) ^ ((ar >> 1) & 3)) << 2;
            ldsm_x4(ah,     smem_u32(&sAhi[buf][ar][aph]));
            ldsm_x4(ah + 4, smem_u32(&sAhi[buf][16 + ar][aph]));
            ldsm_x4(al,     smem_u32(&sAlo[buf][ar][aph]));
            ldsm_x4(al + 4, smem_u32(&sAlo[buf][16 + ar][aph]));
            int br = (lane & 15) + kk * 16;
            int bph = (((w << 1) + (lane >> 4)) ^ (lane & 7)) << 2;
            ldsm_x4_t(bh, smem_u32(&sBhi[buf][br][bph]));
            ldsm_x4_t(bl, smem_u32(&sBlo[buf][br][bph]));
#pragma unroll
            for (int mt = 0; mt < 2; mt++)
#pragma unroll
                for (int nt = 0; nt < 2; nt++)
                    mma_bf16(acc[mt][nt][0], acc[mt][nt][1], acc[mt][nt][2], acc[mt][nt][3],
                             ah[4 * mt], ah[4 * mt + 1], ah[4 * mt + 2], ah[4 * mt + 3],
                             bh[2 * nt], bh[2 * nt + 1]);
#pragma unroll
            for (int mt = 0; mt < 2; mt++)
#pragma unroll
                for (int nt = 0; nt < 2; nt++)
                    mma_bf16(acc[mt][nt][0], acc[mt][nt][1], acc[mt][nt][2], acc[mt][nt][3],
                             ah[4 * mt], ah[4 * mt + 1], ah[4 * mt + 2], ah[4 * mt + 3],
                             bl[2 * nt], bl[2 * nt + 1]);
#pragma unroll
            for (int mt = 0; mt < 2; mt++)
#pragma unroll
                for (int nt = 0; nt < 2; nt++)
                    mma_bf16(acc[mt][nt][0], acc[mt][nt][1], acc[mt][nt][2], acc[mt][nt][3],
                             al[4 * mt], al[4 * mt + 1], al[4 * mt + 2], al[4 * mt + 3],
                             bh[2 * nt], bh[2 * nt + 1]);
        }
        __syncthreads();
    }

    float* gM = g_Mpart[blockIdx.y];
#pragma unroll
    for (int mt = 0; mt < 2; mt++) {
#pragma unroll
        for (int nt = 0; nt < 2; nt++) {
            int c0 = mt * 16 + g;
            int d0 = dbase + w * 16 + nt * 8 + t * 2;
            if (c0 < NOUT) {
                gM[(size_t)c0 * KD + d0]     = acc[mt][nt][0];
                gM[(size_t)c0 * KD + d0 + 1] = acc[mt][nt][1];
            }
            if (c0 + 8 < NOUT) {
                gM[(size_t)(c0 + 8) * KD + d0]     = acc[mt][nt][2];
                gM[(size_t)(c0 + 8) * KD + d0 + 1] = acc[mt][nt][3];
            }
        }
    }
}

// ---------------- k2: logits partials via HMMA + ldmatrix, single-buffered (best R15) ----------------
__global__ __launch_bounds__(256, 2) void k2_tensor(const float* __restrict__ feats) {
    __shared__ u32 sAhi[128][20], sAlo[128][20];
    __shared__ u32 sBhi[32][20],  sBlo[32][20];
    int tid = threadIdx.x, w = tid >> 5, lane = tid & 31;
    int g = lane >> 2, t = lane & 3;
    int rowbase = blockIdx.x * 128;
    int kstart = blockIdx.y * KPER2;

    if (tid < 7 * 20) {
        sBhi[25 + tid / 20][tid % 20] = 0u;
        sBlo[25 + tid / 20][tid % 20] = 0u;
    }

    u32 aHi = smem_u32(&sAhi[w * 16 + (lane & 15)][(lane >> 4) * 4]);
    u32 aLo = smem_u32(&sAlo[w * 16 + (lane & 15)][(lane >> 4) * 4]);
    int bn = ((lane >> 4) << 3) + (lane & 7);
    int bwo = ((lane >> 3) & 1) * 4;
    u32 bHi = smem_u32(&sBhi[bn][bwo]);
    u32 bLo = smem_u32(&sBlo[bn][bwo]);
    const u32 BT = 16 * 20 * 4;

    float acc[4][4];
#pragma unroll
    for (int nt = 0; nt < 4; nt++)
#pragma unroll
        for (int j = 0; j < 4; j++) acc[nt][j] = 0.f;

    float4 fa[4], fb0, fb1;
    {
#pragma unroll
        for (int i = 0; i < 4; i++) {
            int u = tid + 256 * i;
            fa[i] = *(const float4*)(feats + (size_t)(rowbase + (u >> 3)) * KD + kstart + (u & 7) * 4);
        }
        if (tid < 200) {
            size_t off = (size_t)(tid >> 3) * KD + kstart + (tid & 7) * 4;
            fb0 = *(const float4*)(g_Mpart[0] + off);
            fb1 = *(const float4*)(g_Mpart[1] + off);
        }
    }

    for (int ch = 0; ch < K2CH; ch++) {
        __syncthreads();
#pragma unroll
        for (int i = 0; i < 4; i++) {
            int u = tid + 256 * i, row = u >> 3, kq = u & 7;
            u32 h0, l0, h1, l1;
            cvt_split(fa[i].x, fa[i].y, h0, l0);
            cvt_split(fa[i].z, fa[i].w, h1, l1);
            sAhi[row][kq * 2] = h0; sAhi[row][kq * 2 + 1] = h1;
            sAlo[row][kq * 2] = l0; sAlo[row][kq * 2 + 1] = l1;
        }
        if (tid < 200) {
            int c = tid >> 3, kq = tid & 7;
            u32 h0, l0, h1, l1;
            cvt_split(fb0.x + fb1.x, fb0.y + fb1.y, h0, l0);
            cvt_split(fb0.z + fb1.z, fb0.w + fb1.w, h1, l1);
            sBhi[c][kq * 2] = h0; sBhi[c][kq * 2 + 1] = h1;
            sBlo[c][kq * 2] = l0; sBlo[c][kq * 2 + 1] = l1;
        }
        __syncthreads();
        if (ch + 1 < K2CH) {
            int k0 = kstart + (ch + 1) * 32;
#pragma unroll
            for (int i = 0; i < 4; i++) {
                int u = tid + 256 * i;
                fa[i] = *(const float4*)(feats + (size_t)(rowbase + (u >> 3)) * KD + k0 + (u & 7) * 4);
            }
            if (tid < 200) {
                size_t off = (size_t)(tid >> 3) * KD + k0 + (tid & 7) * 4;
                fb0 = *(const float4*)(g_Mpart[0] + off);
                fb1 = *(const float4*)(g_Mpart[1] + off);
            }
        }
#pragma unroll
        for (int kk = 0; kk < 2; kk++) {
            u32 ko = kk * 32;
            u32 ah[4], al[4], bh[8], bl[8];
            ldsm_x4(ah, aHi + ko);
            ldsm_x4(al, aLo + ko);
            ldsm_x4(bh,     bHi + ko);
            ldsm_x4(bh + 4, bHi + BT + ko);
            ldsm_x4(bl,     bLo + ko);
            ldsm_x4(bl + 4, bLo + BT + ko);
#pragma unroll
            for (int nt = 0; nt < 4; nt++)
                mma_bf16(acc[nt][0], acc[nt][1], acc[nt][2], acc[nt][3],
                         ah[0], ah[1], ah[2], ah[3], bh[2 * nt], bh[2 * nt + 1]);
#pragma unroll
            for (int nt = 0; nt < 4; nt++)
                mma_bf16(acc[nt][0], acc[nt][1], acc[nt][2], acc[nt][3],
                         ah[0], ah[1], ah[2], ah[3], bl[2 * nt], bl[2 * nt + 1]);
#pragma unroll
            for (int nt = 0; nt < 4; nt++)
                mma_bf16(acc[nt][0], acc[nt][1], acc[nt][2], acc[nt][3],
                         al[0], al[1], al[2], al[3], bh[2 * nt], bh[2 * nt + 1]);
        }
    }

    float* gp = g_p2 + (size_t)(blockIdx.y * 16 + blockIdx.x) * 4096;
#pragma unroll
    for (int nt = 0; nt < 4; nt++) {
        int rl = w * 16 + g, c0 = nt * 8 + t * 2;
        gp[rl * 32 + c0]           = acc[nt][0];
        gp[rl * 32 + c0 + 1]       = acc[nt][1];
        gp[(rl + 8) * 32 + c0]     = acc[nt][2];
        gp[(rl + 8) * 32 + c0 + 1] = acc[nt][3];
    }
}

// ---------------- k2r: sum 28 seg partials + softmax/argmax/box decode ----------------
__global__ __launch_bounds__(256) void k2r(const float* __restrict__ props) {
    int tid = threadIdx.x, lane = tid & 31;
    int row = blockIdx.x * 8 + (tid >> 5);
    int rg = row >> 7, rl = row & 127;

    float t[NOUT];
#pragma unroll
    for (int c = 0; c < NOUT; c++) t[c] = 0.f;
    if (lane < KSPLIT2) {
        const float* base = g_p2 + (size_t)(lane * 16 + rg) * 4096 + rl * 32;
#pragma unroll
        for (int c = 0; c < NOUT; c++) t[c] = base[c];
    }
#pragma unroll
    for (int c = 0; c < NOUT; c++) {
#pragma unroll
        for (int o = 16; o > 0; o >>= 1) t[c] += __shfl_xor_sync(0xffffffffu, t[c], o);
    }

    if (lane == 0) {
#pragma unroll
        for (int c = 0; c < NOUT; c++) t[c] += g_biasf[c];
        float m = t[0]; int idx = 0;
#pragma unroll
        for (int c = 1; c < NCLS_; c++) { if (t[c] > m) { m = t[c]; idx = c; } }
        float ssum = 0.f;
#pragma unroll
        for (int c = 0; c < NCLS_; c++) ssum += expf(t[c] - m);
        float score = 1.f / ssum;
        bool valid = (idx != 0) && (score >= 0.01f);
        float p0 = props[row * 4 + 0], p1 = props[row * 4 + 1];
        float p2 = props[row * 4 + 2], p3 = props[row * 4 + 3];
        g_score[row] = valid ? score : 0.f;
        g_boxes[row * 4 + 0] = p0 + p2 * t[NCLS_ + 0];
        g_boxes[row * 4 + 1] = p1 + p3 * t[NCLS_ + 1];
        g_boxes[row * 4 + 2] = p2 * expf(t[NCLS_ + 2]);
        g_boxes[row * 4 + 3] = p3 * expf(t[NCLS_ + 3]);
    }
}

// ---------------- k3_pre: stable rank + clip -> sorted arrays ----------------
__global__ __launch_bounds__(512) void k3_pre() {
    __shared__ float sraw[512];
    int b = blockIdx.x, t = threadIdx.x;
    int gi = b * 512 + t;
    float sc = g_score[gi];
    sraw[t] = sc;
    float bx = g_boxes[gi * 4 + 0], by = g_boxes[gi * 4 + 1];
    float bw = g_boxes[gi * 4 + 2], bh = g_boxes[gi * 4 + 3];
    __syncthreads();

    int r = 0;
    for (int i = 0; i < 512; i++) {
        float si = sraw[i];
        r += (si > sc) || (si == sc && i < t);
    }

    float x0 = fminf(fmaxf(bx, 0.f), 599.f);
    float y0 = fminf(fmaxf(by, 0.f), 599.f);
    float x1 = fminf(fmaxf(bx + bw - 1.f, 0.f), 599.f);
    float y1 = fminf(fmaxf(by + bh - 1.f, 0.f), 599.f);
    float area = fmaxf(x1 - x0 + 1.f, 0.f) * fmaxf(y1 - y0 + 1.f, 0.f);

    g_ns[b][r] = sc;
    g_nx0[b][r] = x0; g_ny0[b][r] = y0;
    g_nx1[b][r] = x1; g_ny1[b][r] = y1;
    g_na[b][r] = area;
    g_nord[b][r] = (short)t;
}

// ---------------- k3a: IoU bitmask matrix via ballot ----------------
__global__ __launch_bounds__(256) void k3a() {
    __shared__ float sx0[512], sy0[512], sx1[512], sy1[512], sa[512];
    int b = blockIdx.y, cx = blockIdx.x;
    int tid = threadIdx.x, w = tid >> 5, lane = tid & 31;
    for (int i = tid; i < 512; i += 256) {
        sx0[i] = g_nx0[b][i]; sy0[i] = g_ny0[b][i];
        sx1[i] = g_nx1[b][i]; sy1[i] = g_ny1[b][i];
        sa[i] = g_na[b][i];
    }
    __syncthreads();
    int colbase = cx * 64;
    for (int i = w; i < 512; i += 8) {
        float ix0 = sx0[i], iy0 = sy0[i], ix1 = sx1[i], iy1 = sy1[i], ia = sa[i];
        u32 words[2];
#pragma unroll
        for (int hh = 0; hh < 2; hh++) {
            int c = colbase + hh * 32 + lane;
            float xx0 = fmaxf(ix0, sx0[c]);
            float yy0 = fmaxf(iy0, sy0[c]);
            float xx1 = fminf(ix1, sx1[c]);
            float yy1 = fminf(iy1, sy1[c]);
            float inter = fmaxf(xx1 - xx0 + 1.f, 0.f) * fmaxf(yy1 - yy0 + 1.f, 0.f);
            float iou = inter / (ia + sa[c] - inter + 1e-9f);
            bool bit = (iou > 0.5f) && (c != i);
            words[hh] = __ballot_sync(0xffffffffu, bit);
        }
        if (lane == 0) {
            g_mask[b][i][2 * cx]     = words[0];
            g_mask[b][i][2 * cx + 1] = words[1];
        }
    }
}

// ---------------- k3b: barrier-free serial scan (1 warp) + outputs ----------------
__global__ __launch_bounds__(512) void k3b(float* __restrict__ out) {
    __shared__ __align__(16) u32 smask[512][16];
    __shared__ float ss[512];
    __shared__ short sord_[512];
    __shared__ u32 sRem[16];
    int b = blockIdx.x, t = threadIdx.x;

    {
        const uint4* mp = (const uint4*)g_mask[b][t];
        uint4* sp = (uint4*)smask[t];
        sp[0] = mp[0]; sp[1] = mp[1]; sp[2] = mp[2]; sp[3] = mp[3];
    }
    ss[t] = g_ns[b][t];
    sord_[t] = g_nord[b][t];
    __syncthreads();

    if (t < 32) {
        u32 rem = 0;
        for (int i = 0; i < 512; i++) {
            u32 wv = __shfl_sync(0xffffffffu, rem, i >> 5);
            bool rem_i = (wv >> (i & 31)) & 1u;
            bool alive = (!rem_i) && (ss[i] > 0.f);
            if (alive && t < 16) rem |= smask[i][t];
        }
        if (t < 16) sRem[t] = rem;
    }
    __syncthreads();

    bool keep = !((sRem[t >> 5] >> (t & 31)) & 1u) && (ss[t] > 0.f);
    int orig = sord_[t];
    int go = b * 512 + orig;

    out[go] = keep ? ss[t] : 0.f;

    float obx = g_boxes[go * 4 + 0], oby = g_boxes[go * 4 + 1];
    float obw = g_boxes[go * 4 + 2], obh = g_boxes[go * 4 + 3];
    float* ob = out + NROI + (size_t)go * 4;
    if (keep) {
        ob[0] = obx; ob[1] = oby;
        ob[2] = obx + obw - 1.f;
        ob[3] = oby + obh - 1.f;
    } else {
        ob[0] = 0.f; ob[1] = 0.f; ob[2] = -1.f; ob[3] = -1.f;
    }
}

extern "C" void kernel_launch(void* const* d_in, const int* in_sizes, int n_in,
                              void* d_out, int out_size) {
    (void)in_sizes; (void)n_in; (void)out_size;
    const float* rois  = (const float*)d_in[0];
    const float* props = (const float*)d_in[1];
    const float* W1    = (const float*)d_in[2];
    const float* b1    = (const float*)d_in[3];
    const float* Wc    = (const float*)d_in[4];
    const float* bc    = (const float*)d_in[5];
    const float* Wr    = (const float*)d_in[6];
    const float* br    = (const float*)d_in[7];
    float* out = (float*)d_out;

    k_bias<<<NOUT, 256>>>(b1, Wc, bc, Wr, br);               // launch 1
    k1_tensor<<<dim3(KD / 128, HSPL), 256>>>(W1, Wc, Wr);    // launch 2
    k_dummy<<<1, 32>>>();                                    // launch 3
    k2_tensor<<<dim3(16, KSPLIT2), 256>>>(rois);             // launch 4 -> ncu captures k2
    k2r<<<NROI / 8, 256>>>(props);                           // launch 5
    k3_pre<<<4, 512>>>();                                    // launch 6
    k3a<<<dim3(8, 4), 256>>>();                              // launch 7
    k3b<<<4, 512>>>(out);                                    // launch 8
}